// round 4
// baseline (speedup 1.0000x reference)
#include <cuda_runtime.h>

// Problem constants (fixed by the reference)
#define BB 2
#define TT 2048
#define DD 1024
#define HH 16
#define HD 64
#define QKVD 3072   // 3*D
#define MM (BB*TT)  // 4096 rows

// Scratch (no cudaMalloc allowed): qkv projection result and attention output.
__device__ float g_qkv[(size_t)BB * TT * QKVD];   // ~50.3 MB
__device__ float g_attn[(size_t)BB * TT * DD];    // ~16.8 MB

// ---------------------------------------------------------------------------
// SGEMM: C[M,N] = A[M,K] @ B[N,K]^T + bias[N]
// (torch Linear layout: weight is [N,K] row-major, so both operands K-major)
// 128x128 tile, BK=8, 256 threads, 8x8 micro-tile per thread.
// Requires M%128==0, N%128==0, K%8==0 (all hold here).
// ---------------------------------------------------------------------------
__global__ __launch_bounds__(256) void sgemm_tn(
    const float* __restrict__ A, const float* __restrict__ Bm,
    const float* __restrict__ bias, float* __restrict__ C,
    int M, int N, int K)
{
    __shared__ float As[8][128];  // [k][m]
    __shared__ float Bs[8][128];  // [k][n]

    const int tid = threadIdx.x;
    const int tx = tid & 15;        // n-direction (16)
    const int ty = tid >> 4;        // m-direction (16)
    const int m0 = blockIdx.y * 128;
    const int n0 = blockIdx.x * 128;

    const int lrow = tid >> 1;            // 0..127
    const int lc4  = (tid & 1) * 4;       // 0 or 4

    const float* Ag = A  + (size_t)(m0 + lrow) * K + lc4;
    const float* Bg = Bm + (size_t)(n0 + lrow) * K + lc4;

    float acc[8][8];
    #pragma unroll
    for (int i = 0; i < 8; i++)
        #pragma unroll
        for (int j = 0; j < 8; j++) acc[i][j] = 0.f;

    for (int k0 = 0; k0 < K; k0 += 8) {
        float4 av = *(const float4*)(Ag + k0);
        float4 bv = *(const float4*)(Bg + k0);
        __syncthreads();   // protect previous iteration's smem reads
        As[lc4 + 0][lrow] = av.x; As[lc4 + 1][lrow] = av.y;
        As[lc4 + 2][lrow] = av.z; As[lc4 + 3][lrow] = av.w;
        Bs[lc4 + 0][lrow] = bv.x; Bs[lc4 + 1][lrow] = bv.y;
        Bs[lc4 + 2][lrow] = bv.z; Bs[lc4 + 3][lrow] = bv.w;
        __syncthreads();

        #pragma unroll
        for (int k = 0; k < 8; k++) {
            float af[8], bf[8];
            *(float4*)(af)     = *(const float4*)&As[k][ty * 8];
            *(float4*)(af + 4) = *(const float4*)&As[k][ty * 8 + 4];
            *(float4*)(bf)     = *(const float4*)&Bs[k][tx * 8];
            *(float4*)(bf + 4) = *(const float4*)&Bs[k][tx * 8 + 4];
            #pragma unroll
            for (int i = 0; i < 8; i++)
                #pragma unroll
                for (int j = 0; j < 8; j++)
                    acc[i][j] += af[i] * bf[j];
        }
    }

    // epilogue: add bias, vectorized store
    float bfr[8];
    #pragma unroll
    for (int j = 0; j < 8; j++) bfr[j] = bias[n0 + tx * 8 + j];

    #pragma unroll
    for (int i = 0; i < 8; i++) {
        const int m = m0 + ty * 8 + i;
        float* Cr = C + (size_t)m * N + n0 + tx * 8;
        float4 o0 = make_float4(acc[i][0] + bfr[0], acc[i][1] + bfr[1],
                                acc[i][2] + bfr[2], acc[i][3] + bfr[3]);
        float4 o1 = make_float4(acc[i][4] + bfr[4], acc[i][5] + bfr[5],
                                acc[i][6] + bfr[6], acc[i][7] + bfr[7]);
        *(float4*)(Cr)     = o0;
        *(float4*)(Cr + 4) = o1;
    }
}

// ---------------------------------------------------------------------------
// Flash attention, fp32, causal. One CTA = 64 query rows of one (b,h).
// qkv layout (from projection): [B, T, H*192]; within a head's 192 floats:
// [0,64) = q, [64,128) = k, [128,192) = v.
// smem: Qs (d-major), KP (K tile d-major, reused as P tile k-major), Vs.
// Exactly 48 KB static smem. 256 threads, 4x4 micro-tiles (16x16 thread grid).
// ---------------------------------------------------------------------------
__global__ __launch_bounds__(256) void flash_attn_f32(
    const float* __restrict__ qkv, float* __restrict__ attn)
{
    __shared__ float Qs[64][64];  // [d][q]
    __shared__ float KP[64][64];  // first [d][k] (K tile), then [k][q] (P tile)
    __shared__ float Vs[64][64];  // [k][d]

    const int tid = threadIdx.x;
    const int tx = tid & 15;      // key / headdim direction
    const int ty = tid >> 4;      // query direction
    const int qb = blockIdx.x;    // 0..31 (query block)
    const int bh = blockIdx.y;    // 0..31
    const int b  = bh >> 4;
    const int h  = bh & 15;
    const int q0 = qb * 64;

    const float* base = qkv + (size_t)b * TT * QKVD + h * 192;

    // Load Q tile transposed: Qs[d][q]
    #pragma unroll
    for (int it = 0; it < 4; it++) {
        int idx = it * 256 + tid;          // 0..1023
        int q  = idx >> 4;                 // 0..63
        int d4 = (idx & 15) * 4;           // 0..60
        float4 v = *(const float4*)(base + (size_t)(q0 + q) * QKVD + d4);
        Qs[d4 + 0][q] = v.x; Qs[d4 + 1][q] = v.y;
        Qs[d4 + 2][q] = v.z; Qs[d4 + 3][q] = v.w;
    }

    float m_i[4], l_i[4], accO[4][4];
    #pragma unroll
    for (int i = 0; i < 4; i++) {
        m_i[i] = -1e30f; l_i[i] = 0.f;
        #pragma unroll
        for (int j = 0; j < 4; j++) accO[i][j] = 0.f;
    }
    const float scale = 0.125f;   // 1/sqrt(64)

    const int nkb = qb + 1;       // causal: key blocks 0..qb
    for (int kb = 0; kb < nkb; kb++) {
        const int k0 = kb * 64;

        // Load K tile (transposed, [d][k]) and V tile ([k][d])
        __syncthreads();  // previous iteration done with KP/Vs
        #pragma unroll
        for (int it = 0; it < 4; it++) {
            int idx = it * 256 + tid;
            int kk = idx >> 4;
            int d4 = (idx & 15) * 4;
            const float* krow = base + (size_t)(k0 + kk) * QKVD;
            float4 kv = *(const float4*)(krow + 64 + d4);
            KP[d4 + 0][kk] = kv.x; KP[d4 + 1][kk] = kv.y;
            KP[d4 + 2][kk] = kv.z; KP[d4 + 3][kk] = kv.w;
            float4 vv = *(const float4*)(krow + 128 + d4);
            *(float4*)&Vs[kk][d4] = vv;
        }
        __syncthreads();

        // S tile: s[i][j] = q(ty*4+i) . k(tx*4+j)
        float s[4][4];
        #pragma unroll
        for (int i = 0; i < 4; i++)
            #pragma unroll
            for (int j = 0; j < 4; j++) s[i][j] = 0.f;

        #pragma unroll
        for (int d = 0; d < 64; d++) {
            float qf[4], kf[4];
            *(float4*)qf = *(const float4*)&Qs[d][ty * 4];
            *(float4*)kf = *(const float4*)&KP[d][tx * 4];
            #pragma unroll
            for (int i = 0; i < 4; i++)
                #pragma unroll
                for (int j = 0; j < 4; j++)
                    s[i][j] += qf[i] * kf[j];
        }

        // scale + causal mask (only the diagonal block needs masking)
        const bool diag = (kb == qb);
        #pragma unroll
        for (int i = 0; i < 4; i++) {
            const int qrow = q0 + ty * 4 + i;
            #pragma unroll
            for (int j = 0; j < 4; j++) {
                const int kcol = k0 + tx * 4 + j;
                s[i][j] = (diag && kcol > qrow) ? -1e30f : s[i][j] * scale;
            }
        }

        // Online softmax. Row r is shared by 16 lanes (fixed ty), which sit in
        // one 16-lane half of the warp (tid = ty*16+tx, lane = (ty&1)*16+tx),
        // so xor-shuffles with offsets 1,2,4,8 reduce exactly over the row.
        #pragma unroll
        for (int i = 0; i < 4; i++) {
            float mx = fmaxf(fmaxf(s[i][0], s[i][1]), fmaxf(s[i][2], s[i][3]));
            #pragma unroll
            for (int o = 1; o < 16; o <<= 1)
                mx = fmaxf(mx, __shfl_xor_sync(0xffffffffu, mx, o));
            const float mnew = fmaxf(m_i[i], mx);
            const float alpha = __expf(m_i[i] - mnew);
            m_i[i] = mnew;
            float su = 0.f;
            #pragma unroll
            for (int j = 0; j < 4; j++) {
                s[i][j] = __expf(s[i][j] - mnew);
                su += s[i][j];
            }
            #pragma unroll
            for (int o = 1; o < 16; o <<= 1)
                su += __shfl_xor_sync(0xffffffffu, su, o);
            l_i[i] = l_i[i] * alpha + su;
            #pragma unroll
            for (int j = 0; j < 4; j++) accO[i][j] *= alpha;
        }

        __syncthreads();  // all lanes done reading the K tile
        // Write P into KP, transposed to [k][q]
        #pragma unroll
        for (int i = 0; i < 4; i++)
            #pragma unroll
            for (int j = 0; j < 4; j++)
                KP[tx * 4 + j][ty * 4 + i] = s[i][j];
        __syncthreads();

        // O += P @ V : accO[i][j] over rows (ty*4+i), dims (tx*4+j)
        #pragma unroll
        for (int kk = 0; kk < 64; kk++) {
            float pf[4], vf[4];
            *(float4*)pf = *(const float4*)&KP[kk][ty * 4];
            *(float4*)vf = *(const float4*)&Vs[kk][tx * 4];
            #pragma unroll
            for (int i = 0; i < 4; i++)
                #pragma unroll
                for (int j = 0; j < 4; j++)
                    accO[i][j] += pf[i] * vf[j];
        }
    }

    // Normalize and write out: attn[b, t, h*64 + d]
    #pragma unroll
    for (int i = 0; i < 4; i++) {
        const float inv = 1.f / l_i[i];
        const int t = q0 + ty * 4 + i;
        float* o = attn + (size_t)(b * TT + t) * DD + h * HD + tx * 4;
        *(float4*)o = make_float4(accO[i][0] * inv, accO[i][1] * inv,
                                  accO[i][2] * inv, accO[i][3] * inv);
    }
}

// ---------------------------------------------------------------------------
// Launch: qkv GEMM -> flash attention -> output GEMM
// ---------------------------------------------------------------------------
extern "C" void kernel_launch(void* const* d_in, const int* in_sizes, int n_in,
                              void* d_out, int out_size)
{
    const float* x     = (const float*)d_in[0];  // [B,T,D]
    const float* Wqkv  = (const float*)d_in[1];  // [3D,D]
    const float* bqkv  = (const float*)d_in[2];  // [3D]
    const float* Wout  = (const float*)d_in[3];  // [D,D]
    const float* bout  = (const float*)d_in[4];  // [D]
    float* out = (float*)d_out;                  // [B,T,D]

    float* qkv = nullptr;
    float* attn = nullptr;
    cudaGetSymbolAddress((void**)&qkv, g_qkv);
    cudaGetSymbolAddress((void**)&attn, g_attn);

    // 1) QKV projection: [4096,1024] @ [3072,1024]^T -> [4096,3072]
    sgemm_tn<<<dim3(QKVD / 128, MM / 128), 256>>>(x, Wqkv, bqkv, qkv,
                                                  MM, QKVD, DD);
    // 2) Causal flash attention -> [B,T,D] (head-interleaved output)
    flash_attn_f32<<<dim3(TT / 64, BB * HH), 256>>>(qkv, attn);
    // 3) Output projection: [4096,1024] @ [1024,1024]^T -> [4096,1024]
    sgemm_tn<<<dim3(DD / 128, MM / 128), 256>>>(attn, Wout, bout, out,
                                                MM, DD, DD);
}

// round 7
// speedup vs baseline: 1.5146x; 1.5146x over previous
#include <cuda_runtime.h>
#include <cuda_bf16.h>
#include <cstdint>

// Problem constants (fixed by the reference)
#define BB 2
#define TT 2048
#define DD 1024
#define HH 16
#define HD 64
#define QKVD 3072   // 3*D
#define MM (BB*TT)  // 4096 rows
#define KDIM 1024   // K of both projections

// ---------------------------------------------------------------------------
// Scratch (no cudaMalloc allowed)
// ---------------------------------------------------------------------------
__device__ float g_qkv[(size_t)MM * QKVD];          // fp32 qkv projection
__device__ float g_attn[(size_t)MM * DD];           // fp32 attention output
__device__ __nv_bfloat16 g_xh[(size_t)MM * DD];     // x split
__device__ __nv_bfloat16 g_xl[(size_t)MM * DD];
__device__ __nv_bfloat16 g_wqh[(size_t)QKVD * DD];  // W_qkv split
__device__ __nv_bfloat16 g_wql[(size_t)QKVD * DD];
__device__ __nv_bfloat16 g_woh[(size_t)DD * DD];    // W_out split
__device__ __nv_bfloat16 g_wol[(size_t)DD * DD];
__device__ __nv_bfloat16 g_ah[(size_t)MM * DD];     // attn split
__device__ __nv_bfloat16 g_al[(size_t)MM * DD];

// ---------------------------------------------------------------------------
// Baseline-PTX tensor-core helpers (sm_80-era ISA: compiles for compute_103)
// ---------------------------------------------------------------------------
__device__ __forceinline__ uint32_t smem_to_u32(const void* p) {
    uint32_t a;
    asm("{ .reg .u64 t; cvta.to.shared.u64 t, %1; cvt.u32.u64 %0, t; }"
        : "=r"(a) : "l"(p));
    return a;
}

#define LDSM_X4(r, addr)                                                     \
    asm volatile("ldmatrix.sync.aligned.m8n8.x4.shared.b16 "                 \
        "{%0,%1,%2,%3}, [%4];"                                               \
        : "=r"((r)[0]), "=r"((r)[1]), "=r"((r)[2]), "=r"((r)[3])             \
        : "r"(addr))

#define LDSM_X2(r, addr)                                                     \
    asm volatile("ldmatrix.sync.aligned.m8n8.x2.shared.b16 "                 \
        "{%0,%1}, [%2];"                                                     \
        : "=r"((r)[0]), "=r"((r)[1]) : "r"(addr))

#define MMA16816(d, a, b)                                                    \
    asm volatile("mma.sync.aligned.m16n8k16.row.col.f32.bf16.bf16.f32 "      \
        "{%0,%1,%2,%3}, {%4,%5,%6,%7}, {%8,%9}, {%0,%1,%2,%3};"              \
        : "+f"((d)[0]), "+f"((d)[1]), "+f"((d)[2]), "+f"((d)[3])             \
        : "r"((a)[0]), "r"((a)[1]), "r"((a)[2]), "r"((a)[3]),                \
          "r"((b)[0]), "r"((b)[1]))

#define CP_ASYNC16(dst, src)                                                 \
    asm volatile("cp.async.cg.shared.global [%0], [%1], 16;"                 \
        :: "r"(dst), "l"(src))
#define CP_COMMIT() asm volatile("cp.async.commit_group;" ::: "memory")
#define CP_WAIT1()  asm volatile("cp.async.wait_group 1;"  ::: "memory")
#define CP_WAIT0()  asm volatile("cp.async.wait_group 0;"  ::: "memory")

// ---------------------------------------------------------------------------
// Split fp32 -> bf16 hi + bf16 lo (Markidis split). n % 4 == 0.
// ---------------------------------------------------------------------------
__global__ __launch_bounds__(256) void split_f32(
    const float* __restrict__ s, __nv_bfloat16* __restrict__ h,
    __nv_bfloat16* __restrict__ l, int n)
{
    int i = (blockIdx.x * 256 + threadIdx.x) * 4;
    if (i >= n) return;
    float4 v = *(const float4*)(s + i);
    float x[4] = {v.x, v.y, v.z, v.w};
    __nv_bfloat16 hh[4], ll[4];
    #pragma unroll
    for (int j = 0; j < 4; j++) {
        hh[j] = __float2bfloat16(x[j]);
        ll[j] = __float2bfloat16(x[j] - __bfloat162float(hh[j]));
    }
    *(__nv_bfloat162*)(h + i)     = __nv_bfloat162(hh[0], hh[1]);
    *(__nv_bfloat162*)(h + i + 2) = __nv_bfloat162(hh[2], hh[3]);
    *(__nv_bfloat162*)(l + i)     = __nv_bfloat162(ll[0], ll[1]);
    *(__nv_bfloat162*)(l + i + 2) = __nv_bfloat162(ll[2], ll[3]);
}

// ---------------------------------------------------------------------------
// Tensor-core GEMM via mma.sync (bf16 3-way split, fp32 accum):
//   C[M,N] = (Ah+Al)[M,K] @ (Bh+Bl)[N,K]^T + bias[N]   (Al*Bl dropped)
// 128x128 CTA tile, BK=64 (128B rows, XOR-8 swizzle), 8 warps (2x4),
// warp tile 64x32, 2-stage cp.async pipeline. K = KDIM = 1024.
// smem: stage = {Ah,Al,Bh,Bl} x 16KB = 64KB; 2 stages = 128KB dynamic.
// ---------------------------------------------------------------------------
#define STAGE_BYTES 65536
#define MAT_BYTES   16384

__global__ __launch_bounds__(256, 1) void gemm_mma_split(
    const __nv_bfloat16* __restrict__ Ah, const __nv_bfloat16* __restrict__ Al,
    const __nv_bfloat16* __restrict__ Bh, const __nv_bfloat16* __restrict__ Bl,
    const float* __restrict__ bias, float* __restrict__ C, int N)
{
    extern __shared__ char smem[];
    const uint32_t sb = smem_to_u32(smem);
    const int tid  = threadIdx.x;
    const int lane = tid & 31;
    const int wid  = tid >> 5;
    const int wm   = wid >> 2;     // 0..1 (64-row slab)
    const int wn   = wid & 3;      // 0..3 (32-col slab)
    const int m0 = blockIdx.y * 128;
    const int n0 = blockIdx.x * 128;

    const __nv_bfloat16* const gsrc[4] = {
        Ah + (size_t)m0 * KDIM, Al + (size_t)m0 * KDIM,
        Bh + (size_t)n0 * KDIM, Bl + (size_t)n0 * KDIM };

    float c[4][4][4];
    #pragma unroll
    for (int mt = 0; mt < 4; mt++)
        #pragma unroll
        for (int nt = 0; nt < 4; nt++)
            #pragma unroll
            for (int j = 0; j < 4; j++) c[mt][nt][j] = 0.f;

    // ---- stage loader: 4 matrices x 128 rows x 64 bf16 (8 chunks of 16B) ---
    auto issue = [&](int kc, int stage) {
        const uint32_t sstage = sb + stage * STAGE_BYTES;
        #pragma unroll
        for (int t = 0; t < 4; t++) {
            const __nv_bfloat16* src = gsrc[t] + kc * 64;
            #pragma unroll
            for (int i = 0; i < 4; i++) {
                int u   = i * 256 + tid;    // 0..1023
                int row = u >> 3;           // 0..127
                int ch  = u & 7;            // 16B chunk in row
                const void* g = src + (size_t)row * KDIM + ch * 8;
                uint32_t d = sstage + t * MAT_BYTES + row * 128 +
                             ((ch ^ (row & 7)) << 4);
                CP_ASYNC16(d, g);
            }
        }
        CP_COMMIT();
    };

    // ---- compute on one resident stage -----------------------------------
    auto compute = [&](int stage) {
        const uint32_t sA = sb + stage * STAGE_BYTES;
        #pragma unroll
        for (int ks = 0; ks < 4; ks++) {          // four k16 steps in BK=64
            uint32_t ah[4][4], alr[4][4];
            #pragma unroll
            for (int mt = 0; mt < 4; mt++) {
                int row = wm * 64 + mt * 16 + (lane & 15);
                int ch  = ks * 2 + (lane >> 4);
                uint32_t ad = sA + row * 128 + ((ch ^ (row & 7)) << 4);
                LDSM_X4(ah[mt], ad);
                LDSM_X4(alr[mt], ad + MAT_BYTES);
            }
            uint32_t bhr[4][2], blr[4][2];
            #pragma unroll
            for (int nt = 0; nt < 4; nt++) {
                int rb = wn * 32 + nt * 8 + (lane & 7);
                int cb = ks * 2 + ((lane >> 3) & 1);
                uint32_t bd = sA + 2 * MAT_BYTES + rb * 128 +
                              ((cb ^ (rb & 7)) << 4);
                LDSM_X2(bhr[nt], bd);
                LDSM_X2(blr[nt], bd + MAT_BYTES);
            }
            #pragma unroll
            for (int mt = 0; mt < 4; mt++)
                #pragma unroll
                for (int nt = 0; nt < 4; nt++) {
                    MMA16816(c[mt][nt], ah[mt],  bhr[nt]);
                    MMA16816(c[mt][nt], ah[mt],  blr[nt]);
                    MMA16816(c[mt][nt], alr[mt], bhr[nt]);
                }
        }
    };

    // ---- 2-stage pipeline over 16 K-chunks --------------------------------
    issue(0, 0);
    const int nchunks = KDIM / 64;   // 16
    for (int kc = 0; kc < nchunks; kc++) {
        if (kc + 1 < nchunks) { issue(kc + 1, (kc + 1) & 1); CP_WAIT1(); }
        else                  { CP_WAIT0(); }
        __syncthreads();
        compute(kc & 1);
        __syncthreads();
    }

    // ---- epilogue: add bias, write fp32 -----------------------------------
    #pragma unroll
    for (int mt = 0; mt < 4; mt++) {
        const int r = m0 + wm * 64 + mt * 16 + (lane >> 2);
        #pragma unroll
        for (int nt = 0; nt < 4; nt++) {
            const int cc = n0 + wn * 32 + nt * 8 + (lane & 3) * 2;
            float2 bi = *(const float2*)(bias + cc);
            float2 v0 = make_float2(c[mt][nt][0] + bi.x, c[mt][nt][1] + bi.y);
            float2 v1 = make_float2(c[mt][nt][2] + bi.x, c[mt][nt][3] + bi.y);
            *(float2*)(C + (size_t)r * N + cc)       = v0;
            *(float2*)(C + (size_t)(r + 8) * N + cc) = v1;
        }
    }
}

// ---------------------------------------------------------------------------
// Flash attention, fp32, causal (unchanged, known-correct).
// qkv layout: [B, T, H*192]; per head: [0,64)=q, [64,128)=k, [128,192)=v.
// ---------------------------------------------------------------------------
__global__ __launch_bounds__(256) void flash_attn_f32(
    const float* __restrict__ qkv, float* __restrict__ attn)
{
    __shared__ float Qs[64][64];
    __shared__ float KP[64][64];
    __shared__ float Vs[64][64];

    const int tid = threadIdx.x;
    const int tx = tid & 15;
    const int ty = tid >> 4;
    const int qb = blockIdx.x;
    const int bh = blockIdx.y;
    const int b  = bh >> 4;
    const int h  = bh & 15;
    const int q0 = qb * 64;

    const float* base = qkv + (size_t)b * TT * QKVD + h * 192;

    #pragma unroll
    for (int it = 0; it < 4; it++) {
        int idx = it * 256 + tid;
        int q  = idx >> 4;
        int d4 = (idx & 15) * 4;
        float4 v = *(const float4*)(base + (size_t)(q0 + q) * QKVD + d4);
        Qs[d4 + 0][q] = v.x; Qs[d4 + 1][q] = v.y;
        Qs[d4 + 2][q] = v.z; Qs[d4 + 3][q] = v.w;
    }

    float m_i[4], l_i[4], accO[4][4];
    #pragma unroll
    for (int i = 0; i < 4; i++) {
        m_i[i] = -1e30f; l_i[i] = 0.f;
        #pragma unroll
        for (int j = 0; j < 4; j++) accO[i][j] = 0.f;
    }
    const float scale = 0.125f;

    const int nkb = qb + 1;
    for (int kb = 0; kb < nkb; kb++) {
        const int k0 = kb * 64;

        __syncthreads();
        #pragma unroll
        for (int it = 0; it < 4; it++) {
            int idx = it * 256 + tid;
            int kk = idx >> 4;
            int d4 = (idx & 15) * 4;
            const float* krow = base + (size_t)(k0 + kk) * QKVD;
            float4 kv = *(const float4*)(krow + 64 + d4);
            KP[d4 + 0][kk] = kv.x; KP[d4 + 1][kk] = kv.y;
            KP[d4 + 2][kk] = kv.z; KP[d4 + 3][kk] = kv.w;
            float4 vv = *(const float4*)(krow + 128 + d4);
            *(float4*)&Vs[kk][d4] = vv;
        }
        __syncthreads();

        float s[4][4];
        #pragma unroll
        for (int i = 0; i < 4; i++)
            #pragma unroll
            for (int j = 0; j < 4; j++) s[i][j] = 0.f;

        #pragma unroll
        for (int d = 0; d < 64; d++) {
            float qf[4], kf[4];
            *(float4*)qf = *(const float4*)&Qs[d][ty * 4];
            *(float4*)kf = *(const float4*)&KP[d][tx * 4];
            #pragma unroll
            for (int i = 0; i < 4; i++)
                #pragma unroll
                for (int j = 0; j < 4; j++)
                    s[i][j] += qf[i] * kf[j];
        }

        const bool diag = (kb == qb);
        #pragma unroll
        for (int i = 0; i < 4; i++) {
            const int qrow = q0 + ty * 4 + i;
            #pragma unroll
            for (int j = 0; j < 4; j++) {
                const int kcol = k0 + tx * 4 + j;
                s[i][j] = (diag && kcol > qrow) ? -1e30f : s[i][j] * scale;
            }
        }

        #pragma unroll
        for (int i = 0; i < 4; i++) {
            float mx = fmaxf(fmaxf(s[i][0], s[i][1]), fmaxf(s[i][2], s[i][3]));
            #pragma unroll
            for (int o = 1; o < 16; o <<= 1)
                mx = fmaxf(mx, __shfl_xor_sync(0xffffffffu, mx, o));
            const float mnew = fmaxf(m_i[i], mx);
            const float alpha = __expf(m_i[i] - mnew);
            m_i[i] = mnew;
            float su = 0.f;
            #pragma unroll
            for (int j = 0; j < 4; j++) {
                s[i][j] = __expf(s[i][j] - mnew);
                su += s[i][j];
            }
            #pragma unroll
            for (int o = 1; o < 16; o <<= 1)
                su += __shfl_xor_sync(0xffffffffu, su, o);
            l_i[i] = l_i[i] * alpha + su;
            #pragma unroll
            for (int j = 0; j < 4; j++) accO[i][j] *= alpha;
        }

        __syncthreads();
        #pragma unroll
        for (int i = 0; i < 4; i++)
            #pragma unroll
            for (int j = 0; j < 4; j++)
                KP[tx * 4 + j][ty * 4 + i] = s[i][j];
        __syncthreads();

        #pragma unroll
        for (int kk = 0; kk < 64; kk++) {
            float pf[4], vf[4];
            *(float4*)pf = *(const float4*)&KP[kk][ty * 4];
            *(float4*)vf = *(const float4*)&Vs[kk][tx * 4];
            #pragma unroll
            for (int i = 0; i < 4; i++)
                #pragma unroll
                for (int j = 0; j < 4; j++)
                    accO[i][j] += pf[i] * vf[j];
        }
    }

    #pragma unroll
    for (int i = 0; i < 4; i++) {
        const float inv = 1.f / l_i[i];
        const int t = q0 + ty * 4 + i;
        float* o = attn + (size_t)(b * TT + t) * DD + h * HD + tx * 4;
        *(float4*)o = make_float4(accO[i][0] * inv, accO[i][1] * inv,
                                  accO[i][2] * inv, accO[i][3] * inv);
    }
}

// ---------------------------------------------------------------------------
// Launch pipeline
// ---------------------------------------------------------------------------
extern "C" void kernel_launch(void* const* d_in, const int* in_sizes, int n_in,
                              void* d_out, int out_size)
{
    const float* x    = (const float*)d_in[0];  // [B,T,D]
    const float* Wqkv = (const float*)d_in[1];  // [3D,D]
    const float* bqkv = (const float*)d_in[2];  // [3D]
    const float* Wout = (const float*)d_in[3];  // [D,D]
    const float* bout = (const float*)d_in[4];  // [D]
    float* out = (float*)d_out;                 // [B,T,D]

    float *qkv, *attn;
    __nv_bfloat16 *xh, *xl, *wqh, *wql, *woh, *wol, *ah, *al;
    cudaGetSymbolAddress((void**)&qkv,  g_qkv);
    cudaGetSymbolAddress((void**)&attn, g_attn);
    cudaGetSymbolAddress((void**)&xh,  g_xh);
    cudaGetSymbolAddress((void**)&xl,  g_xl);
    cudaGetSymbolAddress((void**)&wqh, g_wqh);
    cudaGetSymbolAddress((void**)&wql, g_wql);
    cudaGetSymbolAddress((void**)&woh, g_woh);
    cudaGetSymbolAddress((void**)&wol, g_wol);
    cudaGetSymbolAddress((void**)&ah,  g_ah);
    cudaGetSymbolAddress((void**)&al,  g_al);

    cudaFuncSetAttribute(gemm_mma_split,
                         cudaFuncAttributeMaxDynamicSharedMemorySize,
                         2 * STAGE_BYTES);

    // 1) split inputs and weights to bf16 hi/lo
    split_f32<<<(MM * DD) / 1024, 256>>>(x, xh, xl, MM * DD);
    split_f32<<<(QKVD * DD) / 1024, 256>>>(Wqkv, wqh, wql, QKVD * DD);
    split_f32<<<(DD * DD) / 1024, 256>>>(Wout, woh, wol, DD * DD);

    // 2) QKV projection on tensor cores: [4096,1024]x[3072,1024]^T
    gemm_mma_split<<<dim3(QKVD / 128, MM / 128), 256, 2 * STAGE_BYTES>>>(
        xh, xl, wqh, wql, bqkv, qkv, QKVD);

    // 3) causal flash attention (fp32)
    flash_attn_f32<<<dim3(TT / 64, BB * HH), 256>>>(qkv, attn);

    // 4) split attention output, output projection on tensor cores
    split_f32<<<(MM * DD) / 1024, 256>>>(attn, ah, al, MM * DD);
    gemm_mma_split<<<dim3(DD / 128, MM / 128), 256, 2 * STAGE_BYTES>>>(
        ah, al, woh, wol, bout, out, DD);
}

// round 11
// speedup vs baseline: 3.4789x; 2.2969x over previous
#include <cuda_runtime.h>
#include <cuda_bf16.h>
#include <cstdint>

// Problem constants (fixed by the reference)
#define BB 2
#define TT 2048
#define DD 1024
#define HH 16
#define HD 64
#define QKVD 3072   // 3*D
#define MM (BB*TT)  // 4096 rows
#define KDIM 1024   // K of both projections

// ---------------------------------------------------------------------------
// Scratch (no cudaMalloc allowed)
// ---------------------------------------------------------------------------
__device__ __nv_bfloat16 g_xh[(size_t)MM * DD];       // x split
__device__ __nv_bfloat16 g_xl[(size_t)MM * DD];
__device__ __nv_bfloat16 g_wqh[(size_t)QKVD * DD];    // W_qkv split
__device__ __nv_bfloat16 g_wql[(size_t)QKVD * DD];
__device__ __nv_bfloat16 g_woh[(size_t)DD * DD];      // W_out split
__device__ __nv_bfloat16 g_wol[(size_t)DD * DD];
__device__ __nv_bfloat16 g_qkvh[(size_t)MM * QKVD];   // qkv proj, split bf16
__device__ __nv_bfloat16 g_qkvl[(size_t)MM * QKVD];
__device__ __nv_bfloat16 g_ah[(size_t)MM * DD];       // attention out, split
__device__ __nv_bfloat16 g_al[(size_t)MM * DD];

// ---------------------------------------------------------------------------
// Baseline-PTX tensor-core helpers (sm_80-era ISA: compiles for compute_103)
// ---------------------------------------------------------------------------
__device__ __forceinline__ uint32_t smem_to_u32(const void* p) {
    uint32_t a;
    asm("{ .reg .u64 t; cvta.to.shared.u64 t, %1; cvt.u32.u64 %0, t; }"
        : "=r"(a) : "l"(p));
    return a;
}

#define LDSM_X4(r, addr)                                                     \
    asm volatile("ldmatrix.sync.aligned.m8n8.x4.shared.b16 "                 \
        "{%0,%1,%2,%3}, [%4];"                                               \
        : "=r"((r)[0]), "=r"((r)[1]), "=r"((r)[2]), "=r"((r)[3])             \
        : "r"(addr))

#define LDSM_X4_T(r, addr)                                                   \
    asm volatile("ldmatrix.sync.aligned.m8n8.x4.trans.shared.b16 "           \
        "{%0,%1,%2,%3}, [%4];"                                               \
        : "=r"((r)[0]), "=r"((r)[1]), "=r"((r)[2]), "=r"((r)[3])             \
        : "r"(addr))

#define LDSM_X2(r, addr)                                                     \
    asm volatile("ldmatrix.sync.aligned.m8n8.x2.shared.b16 "                 \
        "{%0,%1}, [%2];"                                                     \
        : "=r"((r)[0]), "=r"((r)[1]) : "r"(addr))

#define MMA16816(d, a, b)                                                    \
    asm volatile("mma.sync.aligned.m16n8k16.row.col.f32.bf16.bf16.f32 "      \
        "{%0,%1,%2,%3}, {%4,%5,%6,%7}, {%8,%9}, {%0,%1,%2,%3};"              \
        : "+f"((d)[0]), "+f"((d)[1]), "+f"((d)[2]), "+f"((d)[3])             \
        : "r"((a)[0]), "r"((a)[1]), "r"((a)[2]), "r"((a)[3]),                \
          "r"((b)[0]), "r"((b)[1]))

#define CP_ASYNC16(dst, src)                                                 \
    asm volatile("cp.async.cg.shared.global [%0], [%1], 16;"                 \
        :: "r"(dst), "l"(src))
#define CP_COMMIT() asm volatile("cp.async.commit_group;" ::: "memory")
#define CP_WAIT1()  asm volatile("cp.async.wait_group 1;"  ::: "memory")
#define CP_WAIT0()  asm volatile("cp.async.wait_group 0;"  ::: "memory")

__device__ __forceinline__ uint32_t pack_bf2(__nv_bfloat16 a, __nv_bfloat16 b) {
    return (uint32_t)__bfloat16_as_ushort(a) |
           ((uint32_t)__bfloat16_as_ushort(b) << 16);
}
// split two fp32 into packed bf16 hi pair + bf16 lo (residual) pair
__device__ __forceinline__ void split2(float f0, float f1,
                                       uint32_t& hi, uint32_t& lo) {
    __nv_bfloat16 h0 = __float2bfloat16(f0);
    __nv_bfloat16 h1 = __float2bfloat16(f1);
    float r0 = f0 - __bfloat162float(h0);
    float r1 = f1 - __bfloat162float(h1);
    hi = pack_bf2(h0, h1);
    lo = pack_bf2(__float2bfloat16(r0), __float2bfloat16(r1));
}

// ---------------------------------------------------------------------------
// Split fp32 -> bf16 hi + bf16 lo (Markidis split). n % 4 == 0.
// ---------------------------------------------------------------------------
__global__ __launch_bounds__(256) void split_f32(
    const float* __restrict__ s, __nv_bfloat16* __restrict__ h,
    __nv_bfloat16* __restrict__ l, int n)
{
    int i = (blockIdx.x * 256 + threadIdx.x) * 4;
    if (i >= n) return;
    float4 v = *(const float4*)(s + i);
    float x[4] = {v.x, v.y, v.z, v.w};
    uint32_t h01, l01, h23, l23;
    split2(x[0], x[1], h01, l01);
    split2(x[2], x[3], h23, l23);
    *(uint32_t*)(h + i)     = h01;  *(uint32_t*)(h + i + 2) = h23;
    *(uint32_t*)(l + i)     = l01;  *(uint32_t*)(l + i + 2) = l23;
}

// ---------------------------------------------------------------------------
// Tensor-core GEMM via mma.sync (bf16 3-way split, fp32 accum):
//   C[M,N] = (Ah+Al)[M,K] @ (Bh+Bl)[N,K]^T + bias[N]
// SPLIT_OUT=false: write fp32 C.  SPLIT_OUT=true: write bf16 hi/lo (Ch, Cl).
// 128x128 CTA tile, BK=64 (128B rows, XOR-8 swizzle), 8 warps (2x4),
// warp tile 64x32, 2-stage cp.async pipeline. K = KDIM = 1024.
// ---------------------------------------------------------------------------
#define STAGE_BYTES 65536
#define MAT_BYTES   16384

template<bool SPLIT_OUT>
__global__ __launch_bounds__(256, 1) void gemm_mma_split(
    const __nv_bfloat16* __restrict__ Ah, const __nv_bfloat16* __restrict__ Al,
    const __nv_bfloat16* __restrict__ Bh, const __nv_bfloat16* __restrict__ Bl,
    const float* __restrict__ bias, float* __restrict__ C,
    __nv_bfloat16* __restrict__ Ch, __nv_bfloat16* __restrict__ Cl, int N)
{
    extern __shared__ char smem[];
    const uint32_t sb = smem_to_u32(smem);
    const int tid  = threadIdx.x;
    const int lane = tid & 31;
    const int wid  = tid >> 5;
    const int wm   = wid >> 2;
    const int wn   = wid & 3;
    const int m0 = blockIdx.y * 128;
    const int n0 = blockIdx.x * 128;

    const __nv_bfloat16* const gsrc[4] = {
        Ah + (size_t)m0 * KDIM, Al + (size_t)m0 * KDIM,
        Bh + (size_t)n0 * KDIM, Bl + (size_t)n0 * KDIM };

    float c[4][4][4];
    #pragma unroll
    for (int mt = 0; mt < 4; mt++)
        #pragma unroll
        for (int nt = 0; nt < 4; nt++)
            #pragma unroll
            for (int j = 0; j < 4; j++) c[mt][nt][j] = 0.f;

    auto issue = [&](int kc, int stage) {
        const uint32_t sstage = sb + stage * STAGE_BYTES;
        #pragma unroll
        for (int t = 0; t < 4; t++) {
            const __nv_bfloat16* src = gsrc[t] + kc * 64;
            #pragma unroll
            for (int i = 0; i < 4; i++) {
                int u   = i * 256 + tid;
                int row = u >> 3;
                int ch  = u & 7;
                const void* g = src + (size_t)row * KDIM + ch * 8;
                uint32_t d = sstage + t * MAT_BYTES + row * 128 +
                             ((ch ^ (row & 7)) << 4);
                CP_ASYNC16(d, g);
            }
        }
        CP_COMMIT();
    };

    auto compute = [&](int stage) {
        const uint32_t sA = sb + stage * STAGE_BYTES;
        #pragma unroll
        for (int ks = 0; ks < 4; ks++) {
            uint32_t ah[4][4], alr[4][4];
            #pragma unroll
            for (int mt = 0; mt < 4; mt++) {
                int row = wm * 64 + mt * 16 + (lane & 15);
                int ch  = ks * 2 + (lane >> 4);
                uint32_t ad = sA + row * 128 + ((ch ^ (row & 7)) << 4);
                LDSM_X4(ah[mt], ad);
                LDSM_X4(alr[mt], ad + MAT_BYTES);
            }
            uint32_t bhr[4][2], blr[4][2];
            #pragma unroll
            for (int nt = 0; nt < 4; nt++) {
                int rb = wn * 32 + nt * 8 + (lane & 7);
                int cb = ks * 2 + ((lane >> 3) & 1);
                uint32_t bd = sA + 2 * MAT_BYTES + rb * 128 +
                              ((cb ^ (rb & 7)) << 4);
                LDSM_X2(bhr[nt], bd);
                LDSM_X2(blr[nt], bd + MAT_BYTES);
            }
            #pragma unroll
            for (int mt = 0; mt < 4; mt++)
                #pragma unroll
                for (int nt = 0; nt < 4; nt++) {
                    MMA16816(c[mt][nt], ah[mt],  bhr[nt]);
                    MMA16816(c[mt][nt], ah[mt],  blr[nt]);
                    MMA16816(c[mt][nt], alr[mt], bhr[nt]);
                }
        }
    };

    issue(0, 0);
    const int nchunks = KDIM / 64;
    for (int kc = 0; kc < nchunks; kc++) {
        if (kc + 1 < nchunks) { issue(kc + 1, (kc + 1) & 1); CP_WAIT1(); }
        else                  { CP_WAIT0(); }
        __syncthreads();
        compute(kc & 1);
        __syncthreads();
    }

    #pragma unroll
    for (int mt = 0; mt < 4; mt++) {
        const int r = m0 + wm * 64 + mt * 16 + (lane >> 2);
        #pragma unroll
        for (int nt = 0; nt < 4; nt++) {
            const int cc = n0 + wn * 32 + nt * 8 + (lane & 3) * 2;
            float2 bi = *(const float2*)(bias + cc);
            float v0 = c[mt][nt][0] + bi.x, v1 = c[mt][nt][1] + bi.y;
            float v2 = c[mt][nt][2] + bi.x, v3 = c[mt][nt][3] + bi.y;
            if (!SPLIT_OUT) {
                *(float2*)(C + (size_t)r * N + cc)       = make_float2(v0, v1);
                *(float2*)(C + (size_t)(r + 8) * N + cc) = make_float2(v2, v3);
            } else {
                uint32_t hi, lo;
                split2(v0, v1, hi, lo);
                *(uint32_t*)(Ch + (size_t)r * N + cc) = hi;
                *(uint32_t*)(Cl + (size_t)r * N + cc) = lo;
                split2(v2, v3, hi, lo);
                *(uint32_t*)(Ch + (size_t)(r + 8) * N + cc) = hi;
                *(uint32_t*)(Cl + (size_t)(r + 8) * N + cc) = lo;
            }
        }
    }
}

// ---------------------------------------------------------------------------
// Tensor-core flash attention, causal, bf16 hi/lo split, fp32 accum.
// qkv split layout: [B*T, 3072]; per head h: cols [h*192, h*192+64) = q,
// [+64, +128) = k, [+128, +192) = v.
// CTA: 128 query rows of one (b,h), 8 warps (16 rows each), 64-key tiles,
// double-buffered cp.async K/V. Epilogue writes split bf16 (ah, al).
// ---------------------------------------------------------------------------
#define QT 128
#define KT 64
#define AQH 0
#define AQL 16384
#define AKV0 32768
#define AKV_STRIDE 32768
#define AKH 0
#define AKL 8192
#define AVH 16384
#define AVL 24576
#define ASMEM (32768 + 2 * 32768)   // 96 KB

__global__ __launch_bounds__(256, 1) void flash_attn_mma(
    const __nv_bfloat16* __restrict__ qkvh,
    const __nv_bfloat16* __restrict__ qkvl,
    __nv_bfloat16* __restrict__ ah, __nv_bfloat16* __restrict__ al)
{
    extern __shared__ char smem[];
    const uint32_t sb = smem_to_u32(smem);
    const int tid  = threadIdx.x;
    const int lane = tid & 31;
    const int w    = tid >> 5;
    const int qb   = (int)gridDim.x - 1 - (int)blockIdx.x;  // heavy-first
    const int bh   = blockIdx.y;
    const int b    = bh >> 4;
    const int h    = bh & 15;
    const int q0   = qb * QT;

    const size_t rowbase = (size_t)b * TT;
    const __nv_bfloat16* qh_g = qkvh + rowbase * QKVD + h * 192;
    const __nv_bfloat16* ql_g = qkvl + rowbase * QKVD + h * 192;

    // Q tiles (Qh, Ql): 128 rows x 64 bf16, swizzled 128B rows
    #pragma unroll
    for (int m = 0; m < 2; m++) {
        const __nv_bfloat16* src = m ? ql_g : qh_g;
        uint32_t dst = sb + (m ? AQL : AQH);
        #pragma unroll
        for (int i = 0; i < 4; i++) {
            int u = i * 256 + tid, row = u >> 3, ch = u & 7;
            CP_ASYNC16(dst + row * 128 + ((ch ^ (row & 7)) << 4),
                       src + (size_t)(q0 + row) * QKVD + ch * 8);
        }
    }

    auto load_kv = [&](int kb, int stage) {
        const int k0 = kb * KT;
        const uint32_t sv = sb + AKV0 + stage * AKV_STRIDE;
        const __nv_bfloat16* const srcs[4] = {
            qh_g + 64, ql_g + 64, qh_g + 128, ql_g + 128 };
        #pragma unroll
        for (int m = 0; m < 4; m++) {
            uint32_t dst = sv + m * 8192;
            #pragma unroll
            for (int i = 0; i < 2; i++) {
                int u = i * 256 + tid, row = u >> 3, ch = u & 7;
                CP_ASYNC16(dst + row * 128 + ((ch ^ (row & 7)) << 4),
                           srcs[m] + (size_t)(k0 + row) * QKVD + ch * 8);
            }
        }
        CP_COMMIT();
    };

    load_kv(0, 0);        // Q + kv0 committed as one group
    CP_WAIT0();
    __syncthreads();

    // Q fragments (persist in registers): 4 k16-steps x a[4], hi and lo
    uint32_t qh_f[4][4], ql_f[4][4];
    #pragma unroll
    for (int ks = 0; ks < 4; ks++) {
        int row = w * 16 + (lane & 15);
        int ch  = ks * 2 + (lane >> 4);
        uint32_t off = row * 128 + ((ch ^ (row & 7)) << 4);
        LDSM_X4(qh_f[ks], sb + AQH + off);
        LDSM_X4(ql_f[ks], sb + AQL + off);
    }

    float accO[8][4];
    #pragma unroll
    for (int nt = 0; nt < 8; nt++)
        #pragma unroll
        for (int j = 0; j < 4; j++) accO[nt][j] = 0.f;
    float m0 = -1e30f, m1 = -1e30f, l0 = 0.f, l1 = 0.f;

    const int r0 = q0 + w * 16 + (lane >> 2);   // this thread's row (and r0+8)
    const int nkb = qb * 2 + 2;
    const float scale = 0.125f;

    for (int kb = 0; kb < nkb; kb++) {
        if (kb + 1 < nkb) { load_kv(kb + 1, (kb + 1) & 1); CP_WAIT1(); }
        else              { CP_WAIT0(); }
        __syncthreads();
        const uint32_t sv = sb + AKV0 + (kb & 1) * AKV_STRIDE;
        const int k0 = kb * KT;

        // ---- S = Qh*Kh + Qh*Kl + Ql*Kh  (16 x 64 per warp) ----
        float s[8][4];
        #pragma unroll
        for (int nt = 0; nt < 8; nt++)
            #pragma unroll
            for (int j = 0; j < 4; j++) s[nt][j] = 0.f;

        #pragma unroll
        for (int ks = 0; ks < 4; ks++) {
            #pragma unroll
            for (int nt2 = 0; nt2 < 4; nt2++) {
                int row = nt2 * 16 + ((lane >> 4) & 1) * 8 + (lane & 7);
                int ch  = ks * 2 + ((lane >> 3) & 1);
                uint32_t off = row * 128 + ((ch ^ (row & 7)) << 4);
                uint32_t kh4[4], kl4[4];
                LDSM_X4(kh4, sv + AKH + off);
                LDSM_X4(kl4, sv + AKL + off);
                MMA16816(s[2 * nt2],     qh_f[ks], kh4);
                MMA16816(s[2 * nt2],     qh_f[ks], kl4);
                MMA16816(s[2 * nt2],     ql_f[ks], kh4);
                MMA16816(s[2 * nt2 + 1], qh_f[ks], kh4 + 2);
                MMA16816(s[2 * nt2 + 1], qh_f[ks], kl4 + 2);
                MMA16816(s[2 * nt2 + 1], ql_f[ks], kh4 + 2);
            }
        }

        // ---- scale + causal mask ----
        const bool full = (k0 + KT - 1 <= q0 + w * 16);
        #pragma unroll
        for (int nt = 0; nt < 8; nt++) {
            int col = k0 + nt * 8 + (lane & 3) * 2;
            if (full) {
                s[nt][0] *= scale; s[nt][1] *= scale;
                s[nt][2] *= scale; s[nt][3] *= scale;
            } else {
                s[nt][0] = (col     <= r0)     ? s[nt][0] * scale : -1e30f;
                s[nt][1] = (col + 1 <= r0)     ? s[nt][1] * scale : -1e30f;
                s[nt][2] = (col     <= r0 + 8) ? s[nt][2] * scale : -1e30f;
                s[nt][3] = (col + 1 <= r0 + 8) ? s[nt][3] * scale : -1e30f;
            }
        }

        // ---- online softmax (rows r0, r0+8; quad-lane reductions) ----
        float mx0 = -1e30f, mx1 = -1e30f;
        #pragma unroll
        for (int nt = 0; nt < 8; nt++) {
            mx0 = fmaxf(mx0, fmaxf(s[nt][0], s[nt][1]));
            mx1 = fmaxf(mx1, fmaxf(s[nt][2], s[nt][3]));
        }
        mx0 = fmaxf(mx0, __shfl_xor_sync(0xffffffffu, mx0, 1));
        mx0 = fmaxf(mx0, __shfl_xor_sync(0xffffffffu, mx0, 2));
        mx1 = fmaxf(mx1, __shfl_xor_sync(0xffffffffu, mx1, 1));
        mx1 = fmaxf(mx1, __shfl_xor_sync(0xffffffffu, mx1, 2));
        const float mn0 = fmaxf(m0, mx0), mn1 = fmaxf(m1, mx1);
        const float a0 = __expf(m0 - mn0), a1 = __expf(m1 - mn1);
        m0 = mn0; m1 = mn1;
        float su0 = 0.f, su1 = 0.f;
        #pragma unroll
        for (int nt = 0; nt < 8; nt++) {
            s[nt][0] = __expf(s[nt][0] - m0);
            s[nt][1] = __expf(s[nt][1] - m0);
            s[nt][2] = __expf(s[nt][2] - m1);
            s[nt][3] = __expf(s[nt][3] - m1);
            su0 += s[nt][0] + s[nt][1];
            su1 += s[nt][2] + s[nt][3];
        }
        su0 += __shfl_xor_sync(0xffffffffu, su0, 1);
        su0 += __shfl_xor_sync(0xffffffffu, su0, 2);
        su1 += __shfl_xor_sync(0xffffffffu, su1, 1);
        su1 += __shfl_xor_sync(0xffffffffu, su1, 2);
        l0 = l0 * a0 + su0;
        l1 = l1 * a1 + su1;
        #pragma unroll
        for (int nt = 0; nt < 8; nt++) {
            accO[nt][0] *= a0; accO[nt][1] *= a0;
            accO[nt][2] *= a1; accO[nt][3] *= a1;
        }

        // ---- pack P into A-fragments (hi + residual lo), register-only ----
        uint32_t ph[4][4], pl[4][4];
        #pragma unroll
        for (int t = 0; t < 4; t++) {
            split2(s[2*t][0],     s[2*t][1],     ph[t][0], pl[t][0]);
            split2(s[2*t][2],     s[2*t][3],     ph[t][1], pl[t][1]);
            split2(s[2*t+1][0],   s[2*t+1][1],   ph[t][2], pl[t][2]);
            split2(s[2*t+1][2],   s[2*t+1][3],   ph[t][3], pl[t][3]);
        }

        // ---- O += Ph*Vh + Ph*Vl + Pl*Vh  (V via ldmatrix.trans) ----
        #pragma unroll
        for (int ks = 0; ks < 4; ks++) {
            #pragma unroll
            for (int nt2 = 0; nt2 < 4; nt2++) {
                int row = ks * 16 + ((lane >> 3) & 1) * 8 + (lane & 7);
                int ch  = nt2 * 2 + ((lane >> 4) & 1);
                uint32_t off = row * 128 + ((ch ^ (row & 7)) << 4);
                uint32_t vh4[4], vl4[4];
                LDSM_X4_T(vh4, sv + AVH + off);
                LDSM_X4_T(vl4, sv + AVL + off);
                MMA16816(accO[2 * nt2],     ph[ks], vh4);
                MMA16816(accO[2 * nt2],     ph[ks], vl4);
                MMA16816(accO[2 * nt2],     pl[ks], vh4);
                MMA16816(accO[2 * nt2 + 1], ph[ks], vh4 + 2);
                MMA16816(accO[2 * nt2 + 1], ph[ks], vl4 + 2);
                MMA16816(accO[2 * nt2 + 1], pl[ks], vh4 + 2);
            }
        }
        __syncthreads();   // all warps done with this buffer before reuse
    }

    // ---- epilogue: normalize, split to bf16 hi/lo, write [row][h*64+d] ----
    const float i0 = 1.f / l0, i1 = 1.f / l1;
    #pragma unroll
    for (int nt = 0; nt < 8; nt++) {
        const int col = h * HD + nt * 8 + (lane & 3) * 2;
        uint32_t hi, lo;
        split2(accO[nt][0] * i0, accO[nt][1] * i0, hi, lo);
        size_t o0 = (rowbase + r0) * DD + col;
        *(uint32_t*)(ah + o0) = hi;
        *(uint32_t*)(al + o0) = lo;
        split2(accO[nt][2] * i1, accO[nt][3] * i1, hi, lo);
        size_t o1 = (rowbase + r0 + 8) * DD + col;
        *(uint32_t*)(ah + o1) = hi;
        *(uint32_t*)(al + o1) = lo;
    }
}

// ---------------------------------------------------------------------------
// Launch pipeline
// ---------------------------------------------------------------------------
extern "C" void kernel_launch(void* const* d_in, const int* in_sizes, int n_in,
                              void* d_out, int out_size)
{
    const float* x    = (const float*)d_in[0];  // [B,T,D]
    const float* Wqkv = (const float*)d_in[1];  // [3D,D]
    const float* bqkv = (const float*)d_in[2];  // [3D]
    const float* Wout = (const float*)d_in[3];  // [D,D]
    const float* bout = (const float*)d_in[4];  // [D]
    float* out = (float*)d_out;                 // [B,T,D]

    __nv_bfloat16 *xh, *xl, *wqh, *wql, *woh, *wol, *qvh, *qvl, *ah, *al;
    cudaGetSymbolAddress((void**)&xh,  g_xh);
    cudaGetSymbolAddress((void**)&xl,  g_xl);
    cudaGetSymbolAddress((void**)&wqh, g_wqh);
    cudaGetSymbolAddress((void**)&wql, g_wql);
    cudaGetSymbolAddress((void**)&woh, g_woh);
    cudaGetSymbolAddress((void**)&wol, g_wol);
    cudaGetSymbolAddress((void**)&qvh, g_qkvh);
    cudaGetSymbolAddress((void**)&qvl, g_qkvl);
    cudaGetSymbolAddress((void**)&ah,  g_ah);
    cudaGetSymbolAddress((void**)&al,  g_al);

    cudaFuncSetAttribute(gemm_mma_split<true>,
                         cudaFuncAttributeMaxDynamicSharedMemorySize,
                         2 * STAGE_BYTES);
    cudaFuncSetAttribute(gemm_mma_split<false>,
                         cudaFuncAttributeMaxDynamicSharedMemorySize,
                         2 * STAGE_BYTES);
    cudaFuncSetAttribute(flash_attn_mma,
                         cudaFuncAttributeMaxDynamicSharedMemorySize, ASMEM);

    // 1) split inputs and weights to bf16 hi/lo
    split_f32<<<(MM * DD) / 1024, 256>>>(x, xh, xl, MM * DD);
    split_f32<<<(QKVD * DD) / 1024, 256>>>(Wqkv, wqh, wql, QKVD * DD);
    split_f32<<<(DD * DD) / 1024, 256>>>(Wout, woh, wol, DD * DD);

    // 2) QKV projection -> split bf16 output directly
    gemm_mma_split<true><<<dim3(QKVD / 128, MM / 128), 256, 2 * STAGE_BYTES>>>(
        xh, xl, wqh, wql, bqkv, nullptr, qvh, qvl, QKVD);

    // 3) causal flash attention on tensor cores -> split bf16 output
    flash_attn_mma<<<dim3(TT / QT, BB * HH), 256, ASMEM>>>(qvh, qvl, ah, al);

    // 4) output projection -> fp32 final output
    gemm_mma_split<false><<<dim3(DD / 128, MM / 128), 256, 2 * STAGE_BYTES>>>(
        ah, al, woh, wol, bout, out, nullptr, nullptr, DD);
}

// round 12
// speedup vs baseline: 3.4928x; 1.0040x over previous
#include <cuda_runtime.h>
#include <cuda_bf16.h>
#include <cstdint>

// Problem constants (fixed by the reference)
#define BB 2
#define TT 2048
#define DD 1024
#define HH 16
#define HD 64
#define QKVD 3072   // 3*D
#define MM (BB*TT)  // 4096 rows
#define KDIM 1024   // K of both projections

// ---------------------------------------------------------------------------
// Scratch (no cudaMalloc allowed)
// ---------------------------------------------------------------------------
__device__ __nv_bfloat16 g_xh[(size_t)MM * DD];       // x split
__device__ __nv_bfloat16 g_xl[(size_t)MM * DD];
__device__ __nv_bfloat16 g_wqh[(size_t)QKVD * DD];    // W_qkv split
__device__ __nv_bfloat16 g_wql[(size_t)QKVD * DD];
__device__ __nv_bfloat16 g_woh[(size_t)DD * DD];      // W_out split
__device__ __nv_bfloat16 g_wol[(size_t)DD * DD];
__device__ __nv_bfloat16 g_qkvh[(size_t)MM * QKVD];   // qkv proj, split bf16
__device__ __nv_bfloat16 g_qkvl[(size_t)MM * QKVD];
__device__ __nv_bfloat16 g_ah[(size_t)MM * DD];       // attention out, split
__device__ __nv_bfloat16 g_al[(size_t)MM * DD];

// ---------------------------------------------------------------------------
// Baseline-PTX tensor-core helpers (sm_80-era ISA: compiles for compute_103)
// ---------------------------------------------------------------------------
__device__ __forceinline__ uint32_t smem_to_u32(const void* p) {
    uint32_t a;
    asm("{ .reg .u64 t; cvta.to.shared.u64 t, %1; cvt.u32.u64 %0, t; }"
        : "=r"(a) : "l"(p));
    return a;
}

#define LDSM_X4(r, addr)                                                     \
    asm volatile("ldmatrix.sync.aligned.m8n8.x4.shared.b16 "                 \
        "{%0,%1,%2,%3}, [%4];"                                               \
        : "=r"((r)[0]), "=r"((r)[1]), "=r"((r)[2]), "=r"((r)[3])             \
        : "r"(addr))

#define LDSM_X4_T(r, addr)                                                   \
    asm volatile("ldmatrix.sync.aligned.m8n8.x4.trans.shared.b16 "           \
        "{%0,%1,%2,%3}, [%4];"                                               \
        : "=r"((r)[0]), "=r"((r)[1]), "=r"((r)[2]), "=r"((r)[3])             \
        : "r"(addr))

#define LDSM_X2(r, addr)                                                     \
    asm volatile("ldmatrix.sync.aligned.m8n8.x2.shared.b16 "                 \
        "{%0,%1}, [%2];"                                                     \
        : "=r"((r)[0]), "=r"((r)[1]) : "r"(addr))

#define MMA16816(d, a, b)                                                    \
    asm volatile("mma.sync.aligned.m16n8k16.row.col.f32.bf16.bf16.f32 "      \
        "{%0,%1,%2,%3}, {%4,%5,%6,%7}, {%8,%9}, {%0,%1,%2,%3};"              \
        : "+f"((d)[0]), "+f"((d)[1]), "+f"((d)[2]), "+f"((d)[3])             \
        : "r"((a)[0]), "r"((a)[1]), "r"((a)[2]), "r"((a)[3]),                \
          "r"((b)[0]), "r"((b)[1]))

#define CP_ASYNC16(dst, src)                                                 \
    asm volatile("cp.async.cg.shared.global [%0], [%1], 16;"                 \
        :: "r"(dst), "l"(src))
#define CP_COMMIT() asm volatile("cp.async.commit_group;" ::: "memory")
#define CP_WAIT1()  asm volatile("cp.async.wait_group 1;"  ::: "memory")
#define CP_WAIT0()  asm volatile("cp.async.wait_group 0;"  ::: "memory")

__device__ __forceinline__ float ex2f(float x) {
    float r;
    asm("ex2.approx.f32 %0, %1;" : "=f"(r) : "f"(x));
    return r;
}

__device__ __forceinline__ uint32_t pack_bf2(__nv_bfloat16 a, __nv_bfloat16 b) {
    return (uint32_t)__bfloat16_as_ushort(a) |
           ((uint32_t)__bfloat16_as_ushort(b) << 16);
}
// split two fp32 into packed bf16 hi pair + bf16 lo (residual) pair
__device__ __forceinline__ void split2(float f0, float f1,
                                       uint32_t& hi, uint32_t& lo) {
    __nv_bfloat16 h0 = __float2bfloat16(f0);
    __nv_bfloat16 h1 = __float2bfloat16(f1);
    float r0 = f0 - __bfloat162float(h0);
    float r1 = f1 - __bfloat162float(h1);
    hi = pack_bf2(h0, h1);
    lo = pack_bf2(__float2bfloat16(r0), __float2bfloat16(r1));
}

// ---------------------------------------------------------------------------
// Split fp32 -> bf16 hi + bf16 lo (Markidis split). n % 4 == 0.
// ---------------------------------------------------------------------------
__global__ __launch_bounds__(256) void split_f32(
    const float* __restrict__ s, __nv_bfloat16* __restrict__ h,
    __nv_bfloat16* __restrict__ l, int n)
{
    int i = (blockIdx.x * 256 + threadIdx.x) * 4;
    if (i >= n) return;
    float4 v = *(const float4*)(s + i);
    uint32_t h01, l01, h23, l23;
    split2(v.x, v.y, h01, l01);
    split2(v.z, v.w, h23, l23);
    *(uint32_t*)(h + i)     = h01;  *(uint32_t*)(h + i + 2) = h23;
    *(uint32_t*)(l + i)     = l01;  *(uint32_t*)(l + i + 2) = l23;
}

// ---------------------------------------------------------------------------
// Tensor-core GEMM via mma.sync (bf16 3-way split, fp32 accum):
//   C[M,N] = (Ah+Al)[M,K] @ (Bh+Bl)[N,K]^T + bias[N]
// 128x128 CTA tile, BK=64, 8 warps (2x4), warp tile 64x32.
// 3-stage cp.async pipeline (one __syncthreads per chunk), register
// double-buffered ldmatrix fragments inside the ks loop.
// ---------------------------------------------------------------------------
#define STAGE_BYTES 65536
#define MAT_BYTES   16384

template<bool SPLIT_OUT>
__global__ __launch_bounds__(256, 1) void gemm_mma_split(
    const __nv_bfloat16* __restrict__ Ah, const __nv_bfloat16* __restrict__ Al,
    const __nv_bfloat16* __restrict__ Bh, const __nv_bfloat16* __restrict__ Bl,
    const float* __restrict__ bias, float* __restrict__ C,
    __nv_bfloat16* __restrict__ Ch, __nv_bfloat16* __restrict__ Cl, int N)
{
    extern __shared__ char smem[];
    const uint32_t sb = smem_to_u32(smem);
    const int tid  = threadIdx.x;
    const int lane = tid & 31;
    const int wid  = tid >> 5;
    const int wm   = wid >> 2;
    const int wn   = wid & 3;
    const int m0 = blockIdx.y * 128;
    const int n0 = blockIdx.x * 128;

    const __nv_bfloat16* const gsrc[4] = {
        Ah + (size_t)m0 * KDIM, Al + (size_t)m0 * KDIM,
        Bh + (size_t)n0 * KDIM, Bl + (size_t)n0 * KDIM };

    float c[4][4][4];
    #pragma unroll
    for (int mt = 0; mt < 4; mt++)
        #pragma unroll
        for (int nt = 0; nt < 4; nt++)
            #pragma unroll
            for (int j = 0; j < 4; j++) c[mt][nt][j] = 0.f;

    auto issue = [&](int kc, int stage) {
        const uint32_t sstage = sb + stage * STAGE_BYTES;
        #pragma unroll
        for (int t = 0; t < 4; t++) {
            const __nv_bfloat16* src = gsrc[t] + kc * 64;
            #pragma unroll
            for (int i = 0; i < 4; i++) {
                int u   = i * 256 + tid;
                int row = u >> 3;
                int ch  = u & 7;
                const void* g = src + (size_t)row * KDIM + ch * 8;
                uint32_t d = sstage + t * MAT_BYTES + row * 128 +
                             ((ch ^ (row & 7)) << 4);
                CP_ASYNC16(d, g);
            }
        }
        CP_COMMIT();
    };

    auto ldA = [&](uint32_t sA, int ks, uint32_t (&a)[4][4],
                   uint32_t (&al)[4][4]) {
        #pragma unroll
        for (int mt = 0; mt < 4; mt++) {
            int row = wm * 64 + mt * 16 + (lane & 15);
            int ch  = ks * 2 + (lane >> 4);
            uint32_t ad = sA + row * 128 + ((ch ^ (row & 7)) << 4);
            LDSM_X4(a[mt], ad);
            LDSM_X4(al[mt], ad + MAT_BYTES);
        }
    };
    auto ldB = [&](uint32_t sA, int ks, uint32_t (&bh)[4][2],
                   uint32_t (&bl)[4][2]) {
        #pragma unroll
        for (int nt = 0; nt < 4; nt++) {
            int rb = wn * 32 + nt * 8 + (lane & 7);
            int cb = ks * 2 + ((lane >> 3) & 1);
            uint32_t bd = sA + 2 * MAT_BYTES + rb * 128 +
                          ((cb ^ (rb & 7)) << 4);
            LDSM_X2(bh[nt], bd);
            LDSM_X2(bl[nt], bd + MAT_BYTES);
        }
    };

    auto compute = [&](int stage) {
        const uint32_t sA = sb + stage * STAGE_BYTES;
        uint32_t a_[2][4][4], al_[2][4][4];
        uint32_t bh_[2][4][2], bl_[2][4][2];
        ldA(sA, 0, a_[0], al_[0]);
        ldB(sA, 0, bh_[0], bl_[0]);
        #pragma unroll
        for (int ks = 0; ks < 4; ks++) {
            const int cur = ks & 1, nxt = cur ^ 1;
            if (ks < 3) {
                ldA(sA, ks + 1, a_[nxt], al_[nxt]);
                ldB(sA, ks + 1, bh_[nxt], bl_[nxt]);
            }
            #pragma unroll
            for (int mt = 0; mt < 4; mt++)
                #pragma unroll
                for (int nt = 0; nt < 4; nt++) {
                    MMA16816(c[mt][nt], a_[cur][mt],  bh_[cur][nt]);
                    MMA16816(c[mt][nt], a_[cur][mt],  bl_[cur][nt]);
                    MMA16816(c[mt][nt], al_[cur][mt], bh_[cur][nt]);
                }
        }
    };

    const int nchunks = KDIM / 64;   // 16
    issue(0, 0);
    issue(1, 1);
    CP_WAIT1();
    __syncthreads();
    for (int kc = 0; kc < nchunks; kc++) {
        if (kc + 2 < nchunks) issue(kc + 2, (kc + 2) % 3);
        compute(kc % 3);
        if (kc + 1 < nchunks) {
            if (kc + 2 < nchunks) CP_WAIT1(); else CP_WAIT0();
            __syncthreads();
        }
    }

    #pragma unroll
    for (int mt = 0; mt < 4; mt++) {
        const int r = m0 + wm * 64 + mt * 16 + (lane >> 2);
        #pragma unroll
        for (int nt = 0; nt < 4; nt++) {
            const int cc = n0 + wn * 32 + nt * 8 + (lane & 3) * 2;
            float2 bi = *(const float2*)(bias + cc);
            float v0 = c[mt][nt][0] + bi.x, v1 = c[mt][nt][1] + bi.y;
            float v2 = c[mt][nt][2] + bi.x, v3 = c[mt][nt][3] + bi.y;
            if (!SPLIT_OUT) {
                *(float2*)(C + (size_t)r * N + cc)       = make_float2(v0, v1);
                *(float2*)(C + (size_t)(r + 8) * N + cc) = make_float2(v2, v3);
            } else {
                uint32_t hi, lo;
                split2(v0, v1, hi, lo);
                *(uint32_t*)(Ch + (size_t)r * N + cc) = hi;
                *(uint32_t*)(Cl + (size_t)r * N + cc) = lo;
                split2(v2, v3, hi, lo);
                *(uint32_t*)(Ch + (size_t)(r + 8) * N + cc) = hi;
                *(uint32_t*)(Cl + (size_t)(r + 8) * N + cc) = lo;
            }
        }
    }
}

// ---------------------------------------------------------------------------
// Tensor-core flash attention, causal, bf16 hi/lo split, fp32 accum.
// qkv split layout: [B*T, 3072]; per head h: cols [h*192, h*192+64) = q,
// [+64, +128) = k, [+128, +192) = v.
// CTA: 128 query rows of one (b,h), 8 warps (16 rows each), 64-key tiles,
// 3-stage cp.async K/V (one sync per tile), register-double-buffered
// ldmatrix fragments, base-2 softmax. Epilogue writes split bf16 (ah, al).
// ---------------------------------------------------------------------------
#define QT 128
#define KT 64
#define AQH 0
#define AQL 16384
#define AKV0 32768
#define AKV_STRIDE 32768
#define AKH 0
#define AKL 8192
#define AVH 16384
#define AVL 24576
#define ASMEM (32768 + 3 * 32768)   // 128 KB

__global__ __launch_bounds__(256, 1) void flash_attn_mma(
    const __nv_bfloat16* __restrict__ qkvh,
    const __nv_bfloat16* __restrict__ qkvl,
    __nv_bfloat16* __restrict__ ah, __nv_bfloat16* __restrict__ al)
{
    extern __shared__ char smem[];
    const uint32_t sb = smem_to_u32(smem);
    const int tid  = threadIdx.x;
    const int lane = tid & 31;
    const int w    = tid >> 5;
    const int qb   = (int)gridDim.x - 1 - (int)blockIdx.x;  // heavy-first
    const int bh   = blockIdx.y;
    const int b    = bh >> 4;
    const int h    = bh & 15;
    const int q0   = qb * QT;

    const size_t rowbase = (size_t)b * TT;
    const __nv_bfloat16* qh_g = qkvh + rowbase * QKVD + h * 192;
    const __nv_bfloat16* ql_g = qkvl + rowbase * QKVD + h * 192;

    // Q tiles (Qh, Ql): 128 rows x 64 bf16, swizzled 128B rows
    #pragma unroll
    for (int m = 0; m < 2; m++) {
        const __nv_bfloat16* src = m ? ql_g : qh_g;
        uint32_t dst = sb + (m ? AQL : AQH);
        #pragma unroll
        for (int i = 0; i < 4; i++) {
            int u = i * 256 + tid, row = u >> 3, ch = u & 7;
            CP_ASYNC16(dst + row * 128 + ((ch ^ (row & 7)) << 4),
                       src + (size_t)(q0 + row) * QKVD + ch * 8);
        }
    }

    auto load_kv = [&](int kb, int stage) {
        const int k0 = kb * KT;
        const uint32_t sv = sb + AKV0 + stage * AKV_STRIDE;
        const __nv_bfloat16* const srcs[4] = {
            qh_g + 64, ql_g + 64, qh_g + 128, ql_g + 128 };
        #pragma unroll
        for (int m = 0; m < 4; m++) {
            uint32_t dst = sv + m * 8192;
            #pragma unroll
            for (int i = 0; i < 2; i++) {
                int u = i * 256 + tid, row = u >> 3, ch = u & 7;
                CP_ASYNC16(dst + row * 128 + ((ch ^ (row & 7)) << 4),
                           srcs[m] + (size_t)(k0 + row) * QKVD + ch * 8);
            }
        }
        CP_COMMIT();
    };

    const int nkb = qb * 2 + 2;
    load_kv(0, 0);                        // group 0: Q + kv0
    if (1 < nkb) load_kv(1, 1);           // group 1: kv1
    if (1 < nkb) CP_WAIT1(); else CP_WAIT0();
    __syncthreads();

    // Q fragments (persist in registers): 4 k16-steps x a[4], hi and lo
    uint32_t qh_f[4][4], ql_f[4][4];
    #pragma unroll
    for (int ks = 0; ks < 4; ks++) {
        int row = w * 16 + (lane & 15);
        int ch  = ks * 2 + (lane >> 4);
        uint32_t off = row * 128 + ((ch ^ (row & 7)) << 4);
        LDSM_X4(qh_f[ks], sb + AQH + off);
        LDSM_X4(ql_f[ks], sb + AQL + off);
    }

    float accO[8][4];
    #pragma unroll
    for (int nt = 0; nt < 8; nt++)
        #pragma unroll
        for (int j = 0; j < 4; j++) accO[nt][j] = 0.f;
    float m0 = -1e30f, m1 = -1e30f, l0 = 0.f, l1 = 0.f;

    const int r0 = q0 + w * 16 + (lane >> 2);   // this thread's row (and r0+8)
    const float scale = 0.125f * 1.4426950408889634f;   // fold log2e: base-2

    for (int kb = 0; kb < nkb; kb++) {
        if (kb + 2 < nkb) load_kv(kb + 2, (kb + 2) % 3);
        const uint32_t sv = sb + AKV0 + (kb % 3) * AKV_STRIDE;
        const int k0 = kb * KT;

        // ---- S = Qh*Kh + Qh*Kl + Ql*Kh  (16 x 64 per warp) ----
        float s[8][4];
        #pragma unroll
        for (int nt = 0; nt < 8; nt++)
            #pragma unroll
            for (int j = 0; j < 4; j++) s[nt][j] = 0.f;

        auto ldK = [&](int i, uint32_t (&kh)[4], uint32_t (&kl)[4]) {
            int ks = i >> 2, nt2 = i & 3;
            int row = nt2 * 16 + ((lane >> 4) & 1) * 8 + (lane & 7);
            int ch  = ks * 2 + ((lane >> 3) & 1);
            uint32_t off = row * 128 + ((ch ^ (row & 7)) << 4);
            LDSM_X4(kh, sv + AKH + off);
            LDSM_X4(kl, sv + AKL + off);
        };
        {
            uint32_t kh_[2][4], kl_[2][4];
            ldK(0, kh_[0], kl_[0]);
            #pragma unroll
            for (int i = 0; i < 16; i++) {
                const int cur = i & 1, nxt = cur ^ 1;
                if (i < 15) ldK(i + 1, kh_[nxt], kl_[nxt]);
                const int ks = i >> 2, nt2 = i & 3;
                MMA16816(s[2 * nt2],     qh_f[ks], kh_[cur]);
                MMA16816(s[2 * nt2],     qh_f[ks], kl_[cur]);
                MMA16816(s[2 * nt2],     ql_f[ks], kh_[cur]);
                MMA16816(s[2 * nt2 + 1], qh_f[ks], kh_[cur] + 2);
                MMA16816(s[2 * nt2 + 1], qh_f[ks], kl_[cur] + 2);
                MMA16816(s[2 * nt2 + 1], ql_f[ks], kh_[cur] + 2);
            }
        }

        // ---- scale (base-2) + causal mask ----
        const bool full = (k0 + KT - 1 <= q0 + w * 16);
        #pragma unroll
        for (int nt = 0; nt < 8; nt++) {
            int col = k0 + nt * 8 + (lane & 3) * 2;
            if (full) {
                s[nt][0] *= scale; s[nt][1] *= scale;
                s[nt][2] *= scale; s[nt][3] *= scale;
            } else {
                s[nt][0] = (col     <= r0)     ? s[nt][0] * scale : -1e30f;
                s[nt][1] = (col + 1 <= r0)     ? s[nt][1] * scale : -1e30f;
                s[nt][2] = (col     <= r0 + 8) ? s[nt][2] * scale : -1e30f;
                s[nt][3] = (col + 1 <= r0 + 8) ? s[nt][3] * scale : -1e30f;
            }
        }

        // ---- online softmax, base 2 (rows r0, r0+8; quad reductions) ----
        float mx0 = -1e30f, mx1 = -1e30f;
        #pragma unroll
        for (int nt = 0; nt < 8; nt++) {
            mx0 = fmaxf(mx0, fmaxf(s[nt][0], s[nt][1]));
            mx1 = fmaxf(mx1, fmaxf(s[nt][2], s[nt][3]));
        }
        mx0 = fmaxf(mx0, __shfl_xor_sync(0xffffffffu, mx0, 1));
        mx0 = fmaxf(mx0, __shfl_xor_sync(0xffffffffu, mx0, 2));
        mx1 = fmaxf(mx1, __shfl_xor_sync(0xffffffffu, mx1, 1));
        mx1 = fmaxf(mx1, __shfl_xor_sync(0xffffffffu, mx1, 2));
        const float mn0 = fmaxf(m0, mx0), mn1 = fmaxf(m1, mx1);
        const float a0 = ex2f(m0 - mn0), a1 = ex2f(m1 - mn1);
        m0 = mn0; m1 = mn1;
        float su0 = 0.f, su1 = 0.f;
        #pragma unroll
        for (int nt = 0; nt < 8; nt++) {
            s[nt][0] = ex2f(s[nt][0] - m0);
            s[nt][1] = ex2f(s[nt][1] - m0);
            s[nt][2] = ex2f(s[nt][2] - m1);
            s[nt][3] = ex2f(s[nt][3] - m1);
            su0 += s[nt][0] + s[nt][1];
            su1 += s[nt][2] + s[nt][3];
        }
        su0 += __shfl_xor_sync(0xffffffffu, su0, 1);
        su0 += __shfl_xor_sync(0xffffffffu, su0, 2);
        su1 += __shfl_xor_sync(0xffffffffu, su1, 1);
        su1 += __shfl_xor_sync(0xffffffffu, su1, 2);
        l0 = l0 * a0 + su0;
        l1 = l1 * a1 + su1;
        #pragma unroll
        for (int nt = 0; nt < 8; nt++) {
            accO[nt][0] *= a0; accO[nt][1] *= a0;
            accO[nt][2] *= a1; accO[nt][3] *= a1;
        }

        // ---- pack P into A-fragments (hi + residual lo), register-only ----
        uint32_t ph[4][4], pl[4][4];
        #pragma unroll
        for (int t = 0; t < 4; t++) {
            split2(s[2*t][0],   s[2*t][1],   ph[t][0], pl[t][0]);
            split2(s[2*t][2],   s[2*t][3],   ph[t][1], pl[t][1]);
            split2(s[2*t+1][0], s[2*t+1][1], ph[t][2], pl[t][2]);
            split2(s[2*t+1][2], s[2*t+1][3], ph[t][3], pl[t][3]);
        }

        // ---- O += Ph*Vh + Ph*Vl + Pl*Vh  (V via ldmatrix.trans) ----
        auto ldV = [&](int i, uint32_t (&vh)[4], uint32_t (&vl)[4]) {
            int ks = i >> 2, nt2 = i & 3;
            int row = ks * 16 + ((lane >> 3) & 1) * 8 + (lane & 7);
            int ch  = nt2 * 2 + ((lane >> 4) & 1);
            uint32_t off = row * 128 + ((ch ^ (row & 7)) << 4);
            LDSM_X4_T(vh, sv + AVH + off);
            LDSM_X4_T(vl, sv + AVL + off);
        };
        {
            uint32_t vh_[2][4], vl_[2][4];
            ldV(0, vh_[0], vl_[0]);
            #pragma unroll
            for (int i = 0; i < 16; i++) {
                const int cur = i & 1, nxt = cur ^ 1;
                if (i < 15) ldV(i + 1, vh_[nxt], vl_[nxt]);
                const int ks = i >> 2, nt2 = i & 3;
                MMA16816(accO[2 * nt2],     ph[ks], vh_[cur]);
                MMA16816(accO[2 * nt2],     ph[ks], vl_[cur]);
                MMA16816(accO[2 * nt2],     pl[ks], vh_[cur]);
                MMA16816(accO[2 * nt2 + 1], ph[ks], vh_[cur] + 2);
                MMA16816(accO[2 * nt2 + 1], ph[ks], vl_[cur] + 2);
                MMA16816(accO[2 * nt2 + 1], pl[ks], vh_[cur] + 2);
            }
        }

        if (kb + 1 < nkb) {
            if (kb + 2 < nkb) CP_WAIT1(); else CP_WAIT0();
            __syncthreads();   // kv(kb+1) ready; all warps done with kb%3
        }
    }

    // ---- epilogue: normalize, split to bf16 hi/lo, write [row][h*64+d] ----
    const float i0 = 1.f / l0, i1 = 1.f / l1;
    #pragma unroll
    for (int nt = 0; nt < 8; nt++) {
        const int col = h * HD + nt * 8 + (lane & 3) * 2;
        uint32_t hi, lo;
        split2(accO[nt][0] * i0, accO[nt][1] * i0, hi, lo);
        size_t o0 = (rowbase + r0) * DD + col;
        *(uint32_t*)(ah + o0) = hi;
        *(uint32_t*)(al + o0) = lo;
        split2(accO[nt][2] * i1, accO[nt][3] * i1, hi, lo);
        size_t o1 = (rowbase + r0 + 8) * DD + col;
        *(uint32_t*)(ah + o1) = hi;
        *(uint32_t*)(al + o1) = lo;
    }
}

// ---------------------------------------------------------------------------
// Launch pipeline
// ---------------------------------------------------------------------------
extern "C" void kernel_launch(void* const* d_in, const int* in_sizes, int n_in,
                              void* d_out, int out_size)
{
    const float* x    = (const float*)d_in[0];  // [B,T,D]
    const float* Wqkv = (const float*)d_in[1];  // [3D,D]
    const float* bqkv = (const float*)d_in[2];  // [3D]
    const float* Wout = (const float*)d_in[3];  // [D,D]
    const float* bout = (const float*)d_in[4];  // [D]
    float* out = (float*)d_out;                 // [B,T,D]

    __nv_bfloat16 *xh, *xl, *wqh, *wql, *woh, *wol, *qvh, *qvl, *ah, *al;
    cudaGetSymbolAddress((void**)&xh,  g_xh);
    cudaGetSymbolAddress((void**)&xl,  g_xl);
    cudaGetSymbolAddress((void**)&wqh, g_wqh);
    cudaGetSymbolAddress((void**)&wql, g_wql);
    cudaGetSymbolAddress((void**)&woh, g_woh);
    cudaGetSymbolAddress((void**)&wol, g_wol);
    cudaGetSymbolAddress((void**)&qvh, g_qkvh);
    cudaGetSymbolAddress((void**)&qvl, g_qkvl);
    cudaGetSymbolAddress((void**)&ah,  g_ah);
    cudaGetSymbolAddress((void**)&al,  g_al);

    cudaFuncSetAttribute(gemm_mma_split<true>,
                         cudaFuncAttributeMaxDynamicSharedMemorySize,
                         3 * STAGE_BYTES);
    cudaFuncSetAttribute(gemm_mma_split<false>,
                         cudaFuncAttributeMaxDynamicSharedMemorySize,
                         3 * STAGE_BYTES);
    cudaFuncSetAttribute(flash_attn_mma,
                         cudaFuncAttributeMaxDynamicSharedMemorySize, ASMEM);

    // 1) split inputs and weights to bf16 hi/lo
    split_f32<<<(MM * DD) / 1024, 256>>>(x, xh, xl, MM * DD);
    split_f32<<<(QKVD * DD) / 1024, 256>>>(Wqkv, wqh, wql, QKVD * DD);
    split_f32<<<(DD * DD) / 1024, 256>>>(Wout, woh, wol, DD * DD);

    // 2) QKV projection -> split bf16 output directly
    gemm_mma_split<true><<<dim3(QKVD / 128, MM / 128), 256, 3 * STAGE_BYTES>>>(
        xh, xl, wqh, wql, bqkv, nullptr, qvh, qvl, QKVD);

    // 3) causal flash attention on tensor cores -> split bf16 output
    flash_attn_mma<<<dim3(TT / QT, BB * HH), 256, ASMEM>>>(qvh, qvl, ah, al);

    // 4) output projection -> fp32 final output
    gemm_mma_split<false><<<dim3(DD / 128, MM / 128), 256, 3 * STAGE_BYTES>>>(
        ah, al, woh, wol, bout, out, nullptr, nullptr, DD);
}

// round 13
// speedup vs baseline: 3.6401x; 1.0422x over previous
#include <cuda_runtime.h>
#include <cuda_bf16.h>
#include <cstdint>

// Problem constants (fixed by the reference)
#define BB 2
#define TT 2048
#define DD 1024
#define HH 16
#define HD 64
#define QKVD 3072   // 3*D
#define MM (BB*TT)  // 4096 rows
#define KDIM 1024   // K of both projections

// ---------------------------------------------------------------------------
// Scratch (no cudaMalloc allowed)
// ---------------------------------------------------------------------------
__device__ __nv_bfloat16 g_xh[(size_t)MM * DD];       // x split
__device__ __nv_bfloat16 g_xl[(size_t)MM * DD];
__device__ __nv_bfloat16 g_wqh[(size_t)QKVD * DD];    // W_qkv split
__device__ __nv_bfloat16 g_wql[(size_t)QKVD * DD];
__device__ __nv_bfloat16 g_woh[(size_t)DD * DD];      // W_out split
__device__ __nv_bfloat16 g_wol[(size_t)DD * DD];
__device__ __nv_bfloat16 g_qkvh[(size_t)MM * QKVD];   // qkv proj, split bf16
__device__ __nv_bfloat16 g_qkvl[(size_t)MM * QKVD];
__device__ __nv_bfloat16 g_ah[(size_t)MM * DD];       // attention out, split
__device__ __nv_bfloat16 g_al[(size_t)MM * DD];

// ---------------------------------------------------------------------------
// Baseline-PTX tensor-core helpers (sm_80-era ISA: compiles for compute_103)
// ---------------------------------------------------------------------------
__device__ __forceinline__ uint32_t smem_to_u32(const void* p) {
    uint32_t a;
    asm("{ .reg .u64 t; cvta.to.shared.u64 t, %1; cvt.u32.u64 %0, t; }"
        : "=r"(a) : "l"(p));
    return a;
}

#define LDSM_X4(r, addr)                                                     \
    asm volatile("ldmatrix.sync.aligned.m8n8.x4.shared.b16 "                 \
        "{%0,%1,%2,%3}, [%4];"                                               \
        : "=r"((r)[0]), "=r"((r)[1]), "=r"((r)[2]), "=r"((r)[3])             \
        : "r"(addr))

#define LDSM_X4_T(r, addr)                                                   \
    asm volatile("ldmatrix.sync.aligned.m8n8.x4.trans.shared.b16 "           \
        "{%0,%1,%2,%3}, [%4];"                                               \
        : "=r"((r)[0]), "=r"((r)[1]), "=r"((r)[2]), "=r"((r)[3])             \
        : "r"(addr))

#define MMA16816(d, a, b)                                                    \
    asm volatile("mma.sync.aligned.m16n8k16.row.col.f32.bf16.bf16.f32 "      \
        "{%0,%1,%2,%3}, {%4,%5,%6,%7}, {%8,%9}, {%0,%1,%2,%3};"              \
        : "+f"((d)[0]), "+f"((d)[1]), "+f"((d)[2]), "+f"((d)[3])             \
        : "r"((a)[0]), "r"((a)[1]), "r"((a)[2]), "r"((a)[3]),                \
          "r"((b)[0]), "r"((b)[1]))

#define CP_ASYNC16(dst, src)                                                 \
    asm volatile("cp.async.cg.shared.global [%0], [%1], 16;"                 \
        :: "r"(dst), "l"(src))
#define CP_COMMIT() asm volatile("cp.async.commit_group;" ::: "memory")
#define CP_WAIT1()  asm volatile("cp.async.wait_group 1;"  ::: "memory")
#define CP_WAIT0()  asm volatile("cp.async.wait_group 0;"  ::: "memory")

__device__ __forceinline__ float ex2f(float x) {
    float r;
    asm("ex2.approx.f32 %0, %1;" : "=f"(r) : "f"(x));
    return r;
}

__device__ __forceinline__ uint32_t pack_bf2(__nv_bfloat16 a, __nv_bfloat16 b) {
    return (uint32_t)__bfloat16_as_ushort(a) |
           ((uint32_t)__bfloat16_as_ushort(b) << 16);
}
// split two fp32 into packed bf16 hi pair + bf16 lo (residual) pair
__device__ __forceinline__ void split2(float f0, float f1,
                                       uint32_t& hi, uint32_t& lo) {
    __nv_bfloat16 h0 = __float2bfloat16(f0);
    __nv_bfloat16 h1 = __float2bfloat16(f1);
    float r0 = f0 - __bfloat162float(h0);
    float r1 = f1 - __bfloat162float(h1);
    hi = pack_bf2(h0, h1);
    lo = pack_bf2(__float2bfloat16(r0), __float2bfloat16(r1));
}

// ---------------------------------------------------------------------------
// Split fp32 -> bf16 hi + bf16 lo (Markidis split). n % 4 == 0.
// ---------------------------------------------------------------------------
__global__ __launch_bounds__(256) void split_f32(
    const float* __restrict__ s, __nv_bfloat16* __restrict__ h,
    __nv_bfloat16* __restrict__ l, int n)
{
    int i = (blockIdx.x * 256 + threadIdx.x) * 4;
    if (i >= n) return;
    float4 v = *(const float4*)(s + i);
    uint32_t h01, l01, h23, l23;
    split2(v.x, v.y, h01, l01);
    split2(v.z, v.w, h23, l23);
    *(uint32_t*)(h + i)     = h01;  *(uint32_t*)(h + i + 2) = h23;
    *(uint32_t*)(l + i)     = l01;  *(uint32_t*)(l + i + 2) = l23;
}

// ---------------------------------------------------------------------------
// Tensor-core GEMM via mma.sync (bf16 3-way split, fp32 accum):
//   C[M,N] = (Ah+Al)[M,K] @ (Bh+Bl)[N,K]^T + bias[N]
// 128x256 CTA tile, BK=64, 8 warps (2x4), warp tile 64x64 (4x8 micro-tiles).
// 6 MMA per LDSM_X4 (2x the old 128x128 config). 2-stage cp.async pipeline.
// smem/stage: Ah,Al 16KB each + Bh,Bl 32KB each = 96KB; 2 stages = 192KB.
// ---------------------------------------------------------------------------
#define STAGE_BYTES 98304
#define A_BYTES     16384
#define B_BYTES     32768
#define OFF_AH 0
#define OFF_AL 16384
#define OFF_BH 32768
#define OFF_BL 65536

template<bool SPLIT_OUT>
__global__ __launch_bounds__(256, 1) void gemm_mma_split(
    const __nv_bfloat16* __restrict__ Ah, const __nv_bfloat16* __restrict__ Al,
    const __nv_bfloat16* __restrict__ Bh, const __nv_bfloat16* __restrict__ Bl,
    const float* __restrict__ bias, float* __restrict__ C,
    __nv_bfloat16* __restrict__ Ch, __nv_bfloat16* __restrict__ Cl, int N)
{
    extern __shared__ char smem[];
    const uint32_t sb = smem_to_u32(smem);
    const int tid  = threadIdx.x;
    const int lane = tid & 31;
    const int wid  = tid >> 5;
    const int wm   = wid >> 2;     // 0..1: 64-row slab
    const int wn   = wid & 3;      // 0..3: 64-col slab
    const int m0 = blockIdx.y * 128;
    const int n0 = blockIdx.x * 256;

    const __nv_bfloat16* const gA[2] = {
        Ah + (size_t)m0 * KDIM, Al + (size_t)m0 * KDIM };
    const __nv_bfloat16* const gB[2] = {
        Bh + (size_t)n0 * KDIM, Bl + (size_t)n0 * KDIM };

    float c[4][8][4];
    #pragma unroll
    for (int mt = 0; mt < 4; mt++)
        #pragma unroll
        for (int nt = 0; nt < 8; nt++)
            #pragma unroll
            for (int j = 0; j < 4; j++) c[mt][nt][j] = 0.f;

    // stage loader: A mats 128x64 bf16 (1024 16B units), B mats 256x64 (2048)
    auto issue = [&](int kc, int stage) {
        const uint32_t ss = sb + stage * STAGE_BYTES;
        #pragma unroll
        for (int t = 0; t < 2; t++) {
            const __nv_bfloat16* src = gA[t] + kc * 64;
            #pragma unroll
            for (int i = 0; i < 4; i++) {
                int u = i * 256 + tid, row = u >> 3, ch = u & 7;
                CP_ASYNC16(ss + OFF_AH + t * A_BYTES + row * 128 +
                           ((ch ^ (row & 7)) << 4),
                           src + (size_t)row * KDIM + ch * 8);
            }
        }
        #pragma unroll
        for (int t = 0; t < 2; t++) {
            const __nv_bfloat16* src = gB[t] + kc * 64;
            #pragma unroll
            for (int i = 0; i < 8; i++) {
                int u = i * 256 + tid, row = u >> 3, ch = u & 7;
                CP_ASYNC16(ss + OFF_BH + t * B_BYTES + row * 128 +
                           ((ch ^ (row & 7)) << 4),
                           src + (size_t)row * KDIM + ch * 8);
            }
        }
        CP_COMMIT();
    };

    auto compute = [&](int stage) {
        const uint32_t ss = sb + stage * STAGE_BYTES;
        #pragma unroll
        for (int ks = 0; ks < 4; ks++) {
            // A fragments: 4 m-tiles (16 rows), hi + lo
            uint32_t a_[4][4], al_[4][4];
            #pragma unroll
            for (int mt = 0; mt < 4; mt++) {
                int row = wm * 64 + mt * 16 + (lane & 15);
                int ch  = ks * 2 + (lane >> 4);
                uint32_t ad = ss + OFF_AH + row * 128 + ((ch ^ (row & 7)) << 4);
                LDSM_X4(a_[mt], ad);
                LDSM_X4(al_[mt], ad + A_BYTES);
            }
            // B fragments: 4 n-tile pairs (16 rows each) via X4, hi + lo
            // r[0..1] = even n-tile b-frag, r[2..3] = odd n-tile b-frag
            uint32_t b_[4][4], bl_[4][4];
            #pragma unroll
            for (int p = 0; p < 4; p++) {
                int row = wn * 64 + p * 16 + ((lane >> 4) & 1) * 8 + (lane & 7);
                int ch  = ks * 2 + ((lane >> 3) & 1);
                uint32_t bd = ss + OFF_BH + row * 128 + ((ch ^ (row & 7)) << 4);
                LDSM_X4(b_[p], bd);
                LDSM_X4(bl_[p], bd + B_BYTES);
            }
            #pragma unroll
            for (int mt = 0; mt < 4; mt++)
                #pragma unroll
                for (int p = 0; p < 4; p++) {
                    MMA16816(c[mt][2*p],   a_[mt],  b_[p]);
                    MMA16816(c[mt][2*p],   a_[mt],  bl_[p]);
                    MMA16816(c[mt][2*p],   al_[mt], b_[p]);
                    MMA16816(c[mt][2*p+1], a_[mt],  b_[p] + 2);
                    MMA16816(c[mt][2*p+1], a_[mt],  bl_[p] + 2);
                    MMA16816(c[mt][2*p+1], al_[mt], b_[p] + 2);
                }
        }
    };

    const int nchunks = KDIM / 64;   // 16
    issue(0, 0);
    for (int kc = 0; kc < nchunks; kc++) {
        if (kc + 1 < nchunks) { issue(kc + 1, (kc + 1) & 1); CP_WAIT1(); }
        else                  { CP_WAIT0(); }
        __syncthreads();          // stage kc visible to all warps
        compute(kc & 1);
        __syncthreads();          // all warps done before stage reuse
    }

    #pragma unroll
    for (int mt = 0; mt < 4; mt++) {
        const int r = m0 + wm * 64 + mt * 16 + (lane >> 2);
        #pragma unroll
        for (int nt = 0; nt < 8; nt++) {
            const int cc = n0 + wn * 64 + nt * 8 + (lane & 3) * 2;
            float2 bi = *(const float2*)(bias + cc);
            float v0 = c[mt][nt][0] + bi.x, v1 = c[mt][nt][1] + bi.y;
            float v2 = c[mt][nt][2] + bi.x, v3 = c[mt][nt][3] + bi.y;
            if (!SPLIT_OUT) {
                *(float2*)(C + (size_t)r * N + cc)       = make_float2(v0, v1);
                *(float2*)(C + (size_t)(r + 8) * N + cc) = make_float2(v2, v3);
            } else {
                uint32_t hi, lo;
                split2(v0, v1, hi, lo);
                *(uint32_t*)(Ch + (size_t)r * N + cc) = hi;
                *(uint32_t*)(Cl + (size_t)r * N + cc) = lo;
                split2(v2, v3, hi, lo);
                *(uint32_t*)(Ch + (size_t)(r + 8) * N + cc) = hi;
                *(uint32_t*)(Cl + (size_t)(r + 8) * N + cc) = lo;
            }
        }
    }
}

// ---------------------------------------------------------------------------
// Tensor-core flash attention, causal, bf16 hi/lo split, fp32 accum.
// (unchanged from the passing R12 kernel)
// ---------------------------------------------------------------------------
#define QT 128
#define KT 64
#define AQH 0
#define AQL 16384
#define AKV0 32768
#define AKV_STRIDE 32768
#define AKH 0
#define AKL 8192
#define AVH 16384
#define AVL 24576
#define ASMEM (32768 + 3 * 32768)   // 128 KB

__global__ __launch_bounds__(256, 1) void flash_attn_mma(
    const __nv_bfloat16* __restrict__ qkvh,
    const __nv_bfloat16* __restrict__ qkvl,
    __nv_bfloat16* __restrict__ ah, __nv_bfloat16* __restrict__ al)
{
    extern __shared__ char smem[];
    const uint32_t sb = smem_to_u32(smem);
    const int tid  = threadIdx.x;
    const int lane = tid & 31;
    const int w    = tid >> 5;
    const int qb   = (int)gridDim.x - 1 - (int)blockIdx.x;  // heavy-first
    const int bh   = blockIdx.y;
    const int b    = bh >> 4;
    const int h    = bh & 15;
    const int q0   = qb * QT;

    const size_t rowbase = (size_t)b * TT;
    const __nv_bfloat16* qh_g = qkvh + rowbase * QKVD + h * 192;
    const __nv_bfloat16* ql_g = qkvl + rowbase * QKVD + h * 192;

    #pragma unroll
    for (int m = 0; m < 2; m++) {
        const __nv_bfloat16* src = m ? ql_g : qh_g;
        uint32_t dst = sb + (m ? AQL : AQH);
        #pragma unroll
        for (int i = 0; i < 4; i++) {
            int u = i * 256 + tid, row = u >> 3, ch = u & 7;
            CP_ASYNC16(dst + row * 128 + ((ch ^ (row & 7)) << 4),
                       src + (size_t)(q0 + row) * QKVD + ch * 8);
        }
    }

    auto load_kv = [&](int kb, int stage) {
        const int k0 = kb * KT;
        const uint32_t sv = sb + AKV0 + stage * AKV_STRIDE;
        const __nv_bfloat16* const srcs[4] = {
            qh_g + 64, ql_g + 64, qh_g + 128, ql_g + 128 };
        #pragma unroll
        for (int m = 0; m < 4; m++) {
            uint32_t dst = sv + m * 8192;
            #pragma unroll
            for (int i = 0; i < 2; i++) {
                int u = i * 256 + tid, row = u >> 3, ch = u & 7;
                CP_ASYNC16(dst + row * 128 + ((ch ^ (row & 7)) << 4),
                           srcs[m] + (size_t)(k0 + row) * QKVD + ch * 8);
            }
        }
        CP_COMMIT();
    };

    const int nkb = qb * 2 + 2;
    load_kv(0, 0);
    if (1 < nkb) load_kv(1, 1);
    if (1 < nkb) CP_WAIT1(); else CP_WAIT0();
    __syncthreads();

    uint32_t qh_f[4][4], ql_f[4][4];
    #pragma unroll
    for (int ks = 0; ks < 4; ks++) {
        int row = w * 16 + (lane & 15);
        int ch  = ks * 2 + (lane >> 4);
        uint32_t off = row * 128 + ((ch ^ (row & 7)) << 4);
        LDSM_X4(qh_f[ks], sb + AQH + off);
        LDSM_X4(ql_f[ks], sb + AQL + off);
    }

    float accO[8][4];
    #pragma unroll
    for (int nt = 0; nt < 8; nt++)
        #pragma unroll
        for (int j = 0; j < 4; j++) accO[nt][j] = 0.f;
    float m0 = -1e30f, m1 = -1e30f, l0 = 0.f, l1 = 0.f;

    const int r0 = q0 + w * 16 + (lane >> 2);
    const float scale = 0.125f * 1.4426950408889634f;   // base-2 softmax

    for (int kb = 0; kb < nkb; kb++) {
        if (kb + 2 < nkb) load_kv(kb + 2, (kb + 2) % 3);
        const uint32_t sv = sb + AKV0 + (kb % 3) * AKV_STRIDE;
        const int k0 = kb * KT;

        float s[8][4];
        #pragma unroll
        for (int nt = 0; nt < 8; nt++)
            #pragma unroll
            for (int j = 0; j < 4; j++) s[nt][j] = 0.f;

        auto ldK = [&](int i, uint32_t (&kh)[4], uint32_t (&kl)[4]) {
            int ks = i >> 2, nt2 = i & 3;
            int row = nt2 * 16 + ((lane >> 4) & 1) * 8 + (lane & 7);
            int ch  = ks * 2 + ((lane >> 3) & 1);
            uint32_t off = row * 128 + ((ch ^ (row & 7)) << 4);
            LDSM_X4(kh, sv + AKH + off);
            LDSM_X4(kl, sv + AKL + off);
        };
        {
            uint32_t kh_[2][4], kl_[2][4];
            ldK(0, kh_[0], kl_[0]);
            #pragma unroll
            for (int i = 0; i < 16; i++) {
                const int cur = i & 1, nxt = cur ^ 1;
                if (i < 15) ldK(i + 1, kh_[nxt], kl_[nxt]);
                const int ks = i >> 2, nt2 = i & 3;
                MMA16816(s[2 * nt2],     qh_f[ks], kh_[cur]);
                MMA16816(s[2 * nt2],     qh_f[ks], kl_[cur]);
                MMA16816(s[2 * nt2],     ql_f[ks], kh_[cur]);
                MMA16816(s[2 * nt2 + 1], qh_f[ks], kh_[cur] + 2);
                MMA16816(s[2 * nt2 + 1], qh_f[ks], kl_[cur] + 2);
                MMA16816(s[2 * nt2 + 1], ql_f[ks], kh_[cur] + 2);
            }
        }

        const bool full = (k0 + KT - 1 <= q0 + w * 16);
        #pragma unroll
        for (int nt = 0; nt < 8; nt++) {
            int col = k0 + nt * 8 + (lane & 3) * 2;
            if (full) {
                s[nt][0] *= scale; s[nt][1] *= scale;
                s[nt][2] *= scale; s[nt][3] *= scale;
            } else {
                s[nt][0] = (col     <= r0)     ? s[nt][0] * scale : -1e30f;
                s[nt][1] = (col + 1 <= r0)     ? s[nt][1] * scale : -1e30f;
                s[nt][2] = (col     <= r0 + 8) ? s[nt][2] * scale : -1e30f;
                s[nt][3] = (col + 1 <= r0 + 8) ? s[nt][3] * scale : -1e30f;
            }
        }

        float mx0 = -1e30f, mx1 = -1e30f;
        #pragma unroll
        for (int nt = 0; nt < 8; nt++) {
            mx0 = fmaxf(mx0, fmaxf(s[nt][0], s[nt][1]));
            mx1 = fmaxf(mx1, fmaxf(s[nt][2], s[nt][3]));
        }
        mx0 = fmaxf(mx0, __shfl_xor_sync(0xffffffffu, mx0, 1));
        mx0 = fmaxf(mx0, __shfl_xor_sync(0xffffffffu, mx0, 2));
        mx1 = fmaxf(mx1, __shfl_xor_sync(0xffffffffu, mx1, 1));
        mx1 = fmaxf(mx1, __shfl_xor_sync(0xffffffffu, mx1, 2));
        const float mn0 = fmaxf(m0, mx0), mn1 = fmaxf(m1, mx1);
        const float a0 = ex2f(m0 - mn0), a1 = ex2f(m1 - mn1);
        m0 = mn0; m1 = mn1;
        float su0 = 0.f, su1 = 0.f;
        #pragma unroll
        for (int nt = 0; nt < 8; nt++) {
            s[nt][0] = ex2f(s[nt][0] - m0);
            s[nt][1] = ex2f(s[nt][1] - m0);
            s[nt][2] = ex2f(s[nt][2] - m1);
            s[nt][3] = ex2f(s[nt][3] - m1);
            su0 += s[nt][0] + s[nt][1];
            su1 += s[nt][2] + s[nt][3];
        }
        su0 += __shfl_xor_sync(0xffffffffu, su0, 1);
        su0 += __shfl_xor_sync(0xffffffffu, su0, 2);
        su1 += __shfl_xor_sync(0xffffffffu, su1, 1);
        su1 += __shfl_xor_sync(0xffffffffu, su1, 2);
        l0 = l0 * a0 + su0;
        l1 = l1 * a1 + su1;
        #pragma unroll
        for (int nt = 0; nt < 8; nt++) {
            accO[nt][0] *= a0; accO[nt][1] *= a0;
            accO[nt][2] *= a1; accO[nt][3] *= a1;
        }

        uint32_t ph[4][4], pl[4][4];
        #pragma unroll
        for (int t = 0; t < 4; t++) {
            split2(s[2*t][0],   s[2*t][1],   ph[t][0], pl[t][0]);
            split2(s[2*t][2],   s[2*t][3],   ph[t][1], pl[t][1]);
            split2(s[2*t+1][0], s[2*t+1][1], ph[t][2], pl[t][2]);
            split2(s[2*t+1][2], s[2*t+1][3], ph[t][3], pl[t][3]);
        }

        auto ldV = [&](int i, uint32_t (&vh)[4], uint32_t (&vl)[4]) {
            int ks = i >> 2, nt2 = i & 3;
            int row = ks * 16 + ((lane >> 3) & 1) * 8 + (lane & 7);
            int ch  = nt2 * 2 + ((lane >> 4) & 1);
            uint32_t off = row * 128 + ((ch ^ (row & 7)) << 4);
            LDSM_X4_T(vh, sv + AVH + off);
            LDSM_X4_T(vl, sv + AVL + off);
        };
        {
            uint32_t vh_[2][4], vl_[2][4];
            ldV(0, vh_[0], vl_[0]);
            #pragma unroll
            for (int i = 0; i < 16; i++) {
                const int cur = i & 1, nxt = cur ^ 1;
                if (i < 15) ldV(i + 1, vh_[nxt], vl_[nxt]);
                const int ks = i >> 2, nt2 = i & 3;
                MMA16816(accO[2 * nt2],     ph[ks], vh_[cur]);
                MMA16816(accO[2 * nt2],     ph[ks], vl_[cur]);
                MMA16816(accO[2 * nt2],     pl[ks], vh_[cur]);
                MMA16816(accO[2 * nt2 + 1], ph[ks], vh_[cur] + 2);
                MMA16816(accO[2 * nt2 + 1], ph[ks], vl_[cur] + 2);
                MMA16816(accO[2 * nt2 + 1], pl[ks], vh_[cur] + 2);
            }
        }

        if (kb + 1 < nkb) {
            if (kb + 2 < nkb) CP_WAIT1(); else CP_WAIT0();
            __syncthreads();
        }
    }

    const float i0 = 1.f / l0, i1 = 1.f / l1;
    #pragma unroll
    for (int nt = 0; nt < 8; nt++) {
        const int col = h * HD + nt * 8 + (lane & 3) * 2;
        uint32_t hi, lo;
        split2(accO[nt][0] * i0, accO[nt][1] * i0, hi, lo);
        size_t o0 = (rowbase + r0) * DD + col;
        *(uint32_t*)(ah + o0) = hi;
        *(uint32_t*)(al + o0) = lo;
        split2(accO[nt][2] * i1, accO[nt][3] * i1, hi, lo);
        size_t o1 = (rowbase + r0 + 8) * DD + col;
        *(uint32_t*)(ah + o1) = hi;
        *(uint32_t*)(al + o1) = lo;
    }
}

// ---------------------------------------------------------------------------
// Launch pipeline
// ---------------------------------------------------------------------------
extern "C" void kernel_launch(void* const* d_in, const int* in_sizes, int n_in,
                              void* d_out, int out_size)
{
    const float* x    = (const float*)d_in[0];  // [B,T,D]
    const float* Wqkv = (const float*)d_in[1];  // [3D,D]
    const float* bqkv = (const float*)d_in[2];  // [3D]
    const float* Wout = (const float*)d_in[3];  // [D,D]
    const float* bout = (const float*)d_in[4];  // [D]
    float* out = (float*)d_out;                 // [B,T,D]

    __nv_bfloat16 *xh, *xl, *wqh, *wql, *woh, *wol, *qvh, *qvl, *ah, *al;
    cudaGetSymbolAddress((void**)&xh,  g_xh);
    cudaGetSymbolAddress((void**)&xl,  g_xl);
    cudaGetSymbolAddress((void**)&wqh, g_wqh);
    cudaGetSymbolAddress((void**)&wql, g_wql);
    cudaGetSymbolAddress((void**)&woh, g_woh);
    cudaGetSymbolAddress((void**)&wol, g_wol);
    cudaGetSymbolAddress((void**)&qvh, g_qkvh);
    cudaGetSymbolAddress((void**)&qvl, g_qkvl);
    cudaGetSymbolAddress((void**)&ah,  g_ah);
    cudaGetSymbolAddress((void**)&al,  g_al);

    cudaFuncSetAttribute(gemm_mma_split<true>,
                         cudaFuncAttributeMaxDynamicSharedMemorySize,
                         2 * STAGE_BYTES);
    cudaFuncSetAttribute(gemm_mma_split<false>,
                         cudaFuncAttributeMaxDynamicSharedMemorySize,
                         2 * STAGE_BYTES);
    cudaFuncSetAttribute(flash_attn_mma,
                         cudaFuncAttributeMaxDynamicSharedMemorySize, ASMEM);

    // 1) split inputs and weights to bf16 hi/lo
    split_f32<<<(MM * DD) / 1024, 256>>>(x, xh, xl, MM * DD);
    split_f32<<<(QKVD * DD) / 1024, 256>>>(Wqkv, wqh, wql, QKVD * DD);
    split_f32<<<(DD * DD) / 1024, 256>>>(Wout, woh, wol, DD * DD);

    // 2) QKV projection -> split bf16 output directly (CTA 128x256)
    gemm_mma_split<true><<<dim3(QKVD / 256, MM / 128), 256, 2 * STAGE_BYTES>>>(
        xh, xl, wqh, wql, bqkv, nullptr, qvh, qvl, QKVD);

    // 3) causal flash attention on tensor cores -> split bf16 output
    flash_attn_mma<<<dim3(TT / QT, BB * HH), 256, ASMEM>>>(qvh, qvl, ah, al);

    // 4) output projection -> fp32 final output (CTA 128x256, single wave)
    gemm_mma_split<false><<<dim3(DD / 256, MM / 128), 256, 2 * STAGE_BYTES>>>(
        ah, al, woh, wol, bout, out, nullptr, nullptr, DD);
}